// round 12
// baseline (speedup 1.0000x reference)
#include <cuda_runtime.h>
#include <cuda_fp16.h>
#include <cstdint>

#define DEVINL __device__ __forceinline__

// ---------------- problem sizes ----------------
constexpr int Bb = 32, Ss = 2048, Hh = 1024;
constexpr int M_TOTAL = Bb * Ss;          // 65536
constexpr int BM = 64, BN = 256, BK = 32;    // CTA tile; K-step = 32 elements
constexpr int NSTEPS = Hh / BK;           // 32
constexpr int NT = Hh / BN;               // 4 N-tiles
constexpr int LDH = 40;                   // padded smem row stride in halves (80B)
constexpr int PIPE = 3;                   // cp.async stages
constexpr int NTHREADS = 256;             // 8 warps; 2 CTAs per SM

// ---------------- scratch (no allocs allowed) ----------------
__device__ float  g_ws[Bb * Hh];          // W_s @ dec
__device__ __half g_wh_h[Hh * Hh];        // fp16 W_h
__device__ __half g_enc_h[(size_t)M_TOTAL * Hh];  // fp16 encoder (128 MB)
__device__ float  g_part[NT][M_TOTAL];    // partial scores per N-tile

struct SmemK1 {
    __half A[PIPE][BM][LDH];   // 3*64*80B  = 15,360 B
    __half B[PIPE][BN][LDH];   // 3*256*80B = 61,440 B
    float ws[BN];
    float v[BN];
    float rowsum[BM];
};                             // ~78 KB -> 2 CTAs/SM

// ---------------- helpers ----------------
DEVINL uint32_t smem_u32(const void* p) {
    uint32_t a;
    asm("{ .reg .u64 t; cvta.to.shared.u64 t, %1; cvt.u32.u64 %0, t; }" : "=r"(a) : "l"(p));
    return a;
}
DEVINL float tanh_fast(float x) {
    float r;
    asm("tanh.approx.f32 %0, %1;" : "=f"(r) : "f"(x));
    return r;
}
DEVINL void cp_async16(uint32_t dst, const void* src) {
    asm volatile("cp.async.cg.shared.global [%0], [%1], 16;" :: "r"(dst), "l"(src));
}
DEVINL void cp_commit() { asm volatile("cp.async.commit_group;"); }
DEVINL void cp_wait1()  { asm volatile("cp.async.wait_group 1;"); }

DEVINL void ldmatrix_x4(uint32_t r[4], uint32_t addr) {
    asm volatile("ldmatrix.sync.aligned.m8n8.x4.shared.b16 {%0,%1,%2,%3}, [%4];"
                 : "=r"(r[0]), "=r"(r[1]), "=r"(r[2]), "=r"(r[3]) : "r"(addr));
}
DEVINL void mma_f16(float c[4], const uint32_t a[4], const uint32_t b[2]) {
    asm volatile(
        "mma.sync.aligned.m16n8k16.row.col.f32.f16.f16.f32 "
        "{%0,%1,%2,%3}, {%4,%5,%6,%7}, {%8,%9}, {%0,%1,%2,%3};"
        : "+f"(c[0]), "+f"(c[1]), "+f"(c[2]), "+f"(c[3])
        : "r"(a[0]), "r"(a[1]), "r"(a[2]), "r"(a[3]), "r"(b[0]), "r"(b[1]));
}
DEVINL uint32_t pack_h2(float lo, float hi) {
    __half2 h = __floats2half2_rn(lo, hi);
    return *reinterpret_cast<uint32_t*>(&h);
}

// ================= K0a: W_h -> fp16 =================
__global__ void wh_to_half_kernel(const float* __restrict__ Wh) {
    int i = (blockIdx.x * 256 + threadIdx.x) * 4;
    float4 v = *reinterpret_cast<const float4*>(Wh + i);
    uint2 u;
    u.x = pack_h2(v.x, v.y);
    u.y = pack_h2(v.z, v.w);
    *reinterpret_cast<uint2*>(g_wh_h + i) = u;
}

// ================= K0c: enc -> fp16 (8 elements/thread; F2FP-ALU-bound) =================
__global__ void enc_to_half_kernel(const float* __restrict__ enc) {
    size_t i = ((size_t)blockIdx.x * 256 + threadIdx.x) * 8;
    float4 v0 = *reinterpret_cast<const float4*>(enc + i);
    float4 v1 = *reinterpret_cast<const float4*>(enc + i + 4);
    uint4 u;
    u.x = pack_h2(v0.x, v0.y); u.y = pack_h2(v0.z, v0.w);
    u.z = pack_h2(v1.x, v1.y); u.w = pack_h2(v1.z, v1.w);
    *reinterpret_cast<uint4*>(g_enc_h + i) = u;
}

// ================= K0b: ws[b,:] = W_s @ dec[b,:] — block per b, dec cached in smem =================
__global__ __launch_bounds__(256) void ws_kernel(const float* __restrict__ dec,
                                                 const float* __restrict__ Wsm) {
    __shared__ float dec_s[Hh];
    const int b = blockIdx.x, tid = threadIdx.x;
    const int w = tid >> 5, lane = tid & 31;
    *reinterpret_cast<float4*>(&dec_s[tid * 4]) =
        *reinterpret_cast<const float4*>(dec + (size_t)b * Hh + tid * 4);
    __syncthreads();
#pragma unroll 1
    for (int o = w; o < Hh; o += 8) {
        const float* wr = Wsm + (size_t)o * Hh;
        float acc = 0.f;
#pragma unroll
        for (int i = 0; i < 8; i++) {
            int k = (i * 32 + lane) * 4;
            float4 w4 = *reinterpret_cast<const float4*>(wr + k);
            acc += dec_s[k] * w4.x + dec_s[k + 1] * w4.y
                 + dec_s[k + 2] * w4.z + dec_s[k + 3] * w4.w;
        }
#pragma unroll
        for (int off = 16; off; off >>= 1) acc += __shfl_xor_sync(0xffffffffu, acc, off);
        if (lane == 0) g_ws[b * Hh + o] = acc;
    }
}

// ================= K1: fused fp16 GEMM + tanh + v-dot -> partial scores =================
// 256 threads, 8 warps in 2(m) x 4(n) grid; warp tile 32(M) x 64(N); BK=32; 2 CTAs/SM.
__global__ __launch_bounds__(NTHREADS, 2) void attn_scores_kernel(const float* __restrict__ vvec) {
    extern __shared__ char smraw[];
    SmemK1& sm = *reinterpret_cast<SmemK1*>(smraw);

    const int tid = threadIdx.x, wid = tid >> 5, lane = tid & 31;
    const int g = lane >> 2, t = lane & 3;
    const int wm = (wid >> 2) * 32;       // 2 m-groups of 32 rows
    const int wn = (wid & 3) * 64;        // 4 n-groups of 64 cols
    const int m_base = blockIdx.y * BM;
    const int n_base = blockIdx.x * BN;
    const int b = m_base >> 11;           // 64 | 2048

    for (int i = tid; i < BN; i += NTHREADS) {
        sm.ws[i] = g_ws[b * Hh + n_base + i];
        sm.v[i]  = vvec[n_base + i];
    }
    if (tid < BM) sm.rowsum[tid] = 0.f;

    // cp.async chunk coordinates: 4 chunks of 16B per 64B k-row (BK=32 halves)
    const int rA = tid >> 2, cA = tid & 3;     // rows 0..63, chunk col 0..3
    const __half* srcA = g_enc_h + (size_t)(m_base + rA) * Hh + cA * 8;
    const __half* srcB = g_wh_h  + (size_t)(n_base + rA) * Hh + cA * 8;

    auto issue_stage = [&](int stage, int k0) {
        // A: 64 rows * 4 chunks = 256 -> 1 per thread
        cp_async16(smem_u32(reinterpret_cast<char*>(&sm.A[stage][rA][0]) + cA * 16),
                   srcA + k0);
#pragma unroll
        for (int i = 0; i < 4; i++)   // B rows rA + 64i
            cp_async16(smem_u32(reinterpret_cast<char*>(&sm.B[stage][rA + i * 64][0]) + cA * 16),
                       srcB + (size_t)(i * 64) * Hh + k0);
        cp_commit();
    };

    float acc[2][8][4];
#pragma unroll
    for (int ma = 0; ma < 2; ma++)
#pragma unroll
        for (int na = 0; na < 8; na++)
#pragma unroll
            for (int r = 0; r < 4; r++) acc[ma][na][r] = 0.f;

    // ldmatrix lane offset (row stride 80B: 8 rows shift 16B/row mod 128 -> conflict-free)
    const int lr = lane & 7, sel = lane >> 3;
    const uint32_t lane_off = (uint32_t)((lr + (sel & 1) * 8) * (LDH * 2) + (sel >> 1) * 16);
    const uint32_t baseA = smem_u32(&sm.A[0][0][0]);
    const uint32_t baseB = smem_u32(&sm.B[0][0][0]);
    constexpr uint32_t A_STRIDE = BM * LDH * 2;   // bytes per stage
    constexpr uint32_t B_STRIDE = BN * LDH * 2;

    // prologue: fill stages 0,1
    issue_stage(0, 0);
    issue_stage(1, BK);

    int p = 0;
#pragma unroll 1
    for (int s = 0; s < NSTEPS; s++) {
        cp_wait1();          // stage s complete (<=1 group in flight)
        __syncthreads();     // visible to all; also: all reads of buffer (s-1) finished

        if (s + 2 < NSTEPS) {
            int nxt = p + 2; if (nxt >= PIPE) nxt -= PIPE;
            issue_stage(nxt, (s + 2) * BK);   // overwrites buffer (s-1): safe after sync
        } else {
            cp_commit();                      // empty group keeps accounting uniform
        }

        uint32_t aw = baseA + p * A_STRIDE + (uint32_t)(wm * (LDH * 2)) + lane_off;
        uint32_t bw = baseB + p * B_STRIDE + (uint32_t)(wn * (LDH * 2)) + lane_off;
#pragma unroll
        for (int ka = 0; ka < 2; ka++) {      // 2 x k16 per stage
            uint32_t af[2][4];
#pragma unroll
            for (int ma = 0; ma < 2; ma++)
                ldmatrix_x4(af[ma], aw + (uint32_t)(ma * 16 * (LDH * 2)) + ka * 32);
            uint32_t bf[8][2];
#pragma unroll
            for (int nb = 0; nb < 4; nb++) {
                uint32_t r[4];
                ldmatrix_x4(r, bw + (uint32_t)(nb * 16 * (LDH * 2)) + ka * 32);
                bf[2 * nb][0] = r[0]; bf[2 * nb + 1][0] = r[1];
                bf[2 * nb][1] = r[2]; bf[2 * nb + 1][1] = r[3];
            }
#pragma unroll
            for (int ma = 0; ma < 2; ma++)
#pragma unroll
                for (int na = 0; na < 8; na++)
                    mma_f16(acc[ma][na], af[ma], bf[na]);
        }

        if (++p >= PIPE) p = 0;
    }

    // epilogue: tanh(acc + ws)*v, reduce over n
#pragma unroll
    for (int ma = 0; ma < 2; ma++) {
        float r0 = 0.f, r1 = 0.f;
#pragma unroll
        for (int na = 0; na < 8; na++) {
            int nl = wn + na * 8 + 2 * t;
            float w0 = sm.ws[nl], w1 = sm.ws[nl + 1];
            float v0 = sm.v[nl],  v1 = sm.v[nl + 1];
            r0 += tanh_fast(acc[ma][na][0] + w0) * v0 + tanh_fast(acc[ma][na][1] + w1) * v1;
            r1 += tanh_fast(acc[ma][na][2] + w0) * v0 + tanh_fast(acc[ma][na][3] + w1) * v1;
        }
        r0 += __shfl_xor_sync(0xffffffffu, r0, 1);
        r0 += __shfl_xor_sync(0xffffffffu, r0, 2);
        r1 += __shfl_xor_sync(0xffffffffu, r1, 1);
        r1 += __shfl_xor_sync(0xffffffffu, r1, 2);
        if (t == 0) {
            atomicAdd(&sm.rowsum[wm + ma * 16 + g], r0);
            atomicAdd(&sm.rowsum[wm + ma * 16 + g + 8], r1);
        }
    }
    __syncthreads();
    if (tid < BM) g_part[blockIdx.x][m_base + tid] = sm.rowsum[tid];
}

// ================= K2: softmax over S per batch =================
__global__ void softmax_kernel(float* __restrict__ wout) {
    __shared__ float sc[Ss];
    __shared__ float red[256];
    int b = blockIdx.x, tid = threadIdx.x;
    float mx = -1e30f;
    for (int i = tid; i < Ss; i += 256) {
        int idx = b * Ss + i;
        float v = g_part[0][idx] + g_part[1][idx] + g_part[2][idx] + g_part[3][idx];
        sc[i] = v;
        mx = fmaxf(mx, v);
    }
    red[tid] = mx; __syncthreads();
    for (int o = 128; o; o >>= 1) { if (tid < o) red[tid] = fmaxf(red[tid], red[tid + o]); __syncthreads(); }
    mx = red[0]; __syncthreads();
    float sum = 0.f;
    for (int i = tid; i < Ss; i += 256) { float e = __expf(sc[i] - mx); sc[i] = e; sum += e; }
    red[tid] = sum; __syncthreads();
    for (int o = 128; o; o >>= 1) { if (tid < o) red[tid] += red[tid + o]; __syncthreads(); }
    float inv = 1.f / red[0];
    for (int i = tid; i < Ss; i += 256) wout[b * Ss + i] = sc[i] * inv;
}

// ================= K3a: zero ctx region (out poisoned by harness) =================
__global__ void zero_ctx_kernel(float* __restrict__ ctx) {
    ctx[blockIdx.x * 256 + threadIdx.x] = 0.f;
}

// ================= K3b: context, s-split x4 with atomicAdd (fp16 enc) =================
__global__ void context_kernel(const float* __restrict__ w, float* __restrict__ out) {
    __shared__ float wsh[512];
    int b = blockIdx.y;
    int s0 = blockIdx.z * 512;
    int h2 = blockIdx.x * 256 + threadIdx.x;   // half2 column index, 0..511
    for (int i = threadIdx.x; i < 512; i += 256) wsh[i] = w[b * Ss + s0 + i];
    __syncthreads();
    const __half2* e = reinterpret_cast<const __half2*>(g_enc_h)
                     + (size_t)b * Ss * (Hh / 2) + (size_t)s0 * (Hh / 2) + h2;
    float a0 = 0.f, a1 = 0.f, b0 = 0.f, b1 = 0.f;
#pragma unroll 4
    for (int s = 0; s < 512; s += 2) {
        float2 f0 = __half22float2(e[(size_t)s * (Hh / 2)]);
        float2 f1 = __half22float2(e[(size_t)(s + 1) * (Hh / 2)]);
        a0 += wsh[s] * f0.x;     a1 += wsh[s] * f0.y;
        b0 += wsh[s + 1] * f1.x; b1 += wsh[s + 1] * f1.y;
    }
    atomicAdd(&out[b * Hh + 2 * h2],     a0 + b0);
    atomicAdd(&out[b * Hh + 2 * h2 + 1], a1 + b1);
}

// ================= launcher =================
extern "C" void kernel_launch(void* const* d_in, const int* in_sizes, int n_in,
                              void* d_out, int out_size) {
    (void)in_sizes; (void)n_in; (void)out_size;
    const float* dec = (const float*)d_in[0];   // [32,1024]
    const float* enc = (const float*)d_in[1];   // [32,2048,1024]
    const float* Wh  = (const float*)d_in[2];   // [1024,1024]
    const float* Wsm = (const float*)d_in[3];   // [1024,1024]
    const float* v   = (const float*)d_in[4];   // [1024]
    float* out  = (float*)d_out;
    float* ctx  = out;                 // [32,1024]
    float* attw = out + Bb * Hh;       // [32,2048]

    cudaFuncSetAttribute(attn_scores_kernel, cudaFuncAttributeMaxDynamicSharedMemorySize,
                         (int)sizeof(SmemK1));

    wh_to_half_kernel<<<Hh * Hh / 1024, 256>>>(Wh);
    enc_to_half_kernel<<<(int)((size_t)M_TOTAL * Hh / 2048), 256>>>(enc);
    ws_kernel<<<Bb, 256>>>(dec, Wsm);
    zero_ctx_kernel<<<Bb * Hh / 256, 256>>>(ctx);
    attn_scores_kernel<<<dim3(NT, M_TOTAL / BM), NTHREADS, sizeof(SmemK1)>>>(v);
    softmax_kernel<<<Bb, 256>>>(attw);
    context_kernel<<<dim3(Hh / 512, Bb, 4), 256>>>(attw, ctx);
}

// round 13
// speedup vs baseline: 1.3211x; 1.3211x over previous
#include <cuda_runtime.h>
#include <cuda_fp16.h>
#include <cstdint>

#define DEVINL __device__ __forceinline__

// ---------------- problem sizes ----------------
constexpr int Bb = 32, Ss = 2048, Hh = 1024;
constexpr int M_TOTAL = Bb * Ss;          // 65536
constexpr int BM = 128, BN = 256, BK = 64;   // K-step = 64 elements
constexpr int NSTEPS = Hh / BK;           // 16
constexpr int NT = Hh / BN;               // 4 N-tiles
constexpr int LDH = 72;                   // padded smem row stride in halves (144B)
constexpr int PIPE = 3;                   // cp.async stages
constexpr int NTHREADS = 512;             // 16 warps

// ---------------- scratch (no allocs allowed) ----------------
__device__ float  g_ws[Bb * Hh];          // W_s @ dec
__device__ __half g_wh_h[Hh * Hh];        // fp16 W_h
__device__ __half g_enc_h[(size_t)M_TOTAL * Hh];  // fp16 encoder (128 MB)
__device__ float  g_part[NT][M_TOTAL];    // partial scores per N-tile

struct SmemK1 {
    __half A[PIPE][BM][LDH];   // 3*128*144B = 55,296 B
    __half B[PIPE][BN][LDH];   // 3*256*144B = 110,592 B
    float ws[BN];
    float v[BN];
    float rowsum[BM];
};

// ---------------- helpers ----------------
DEVINL uint32_t smem_u32(const void* p) {
    uint32_t a;
    asm("{ .reg .u64 t; cvta.to.shared.u64 t, %1; cvt.u32.u64 %0, t; }" : "=r"(a) : "l"(p));
    return a;
}
DEVINL float tanh_fast(float x) {
    float r;
    asm("tanh.approx.f32 %0, %1;" : "=f"(r) : "f"(x));
    return r;
}
DEVINL void cp_async16(uint32_t dst, const void* src) {
    asm volatile("cp.async.cg.shared.global [%0], [%1], 16;" :: "r"(dst), "l"(src));
}
DEVINL void cp_commit() { asm volatile("cp.async.commit_group;"); }
DEVINL void cp_wait1()  { asm volatile("cp.async.wait_group 1;"); }

DEVINL void ldmatrix_x4(uint32_t r[4], uint32_t addr) {
    asm volatile("ldmatrix.sync.aligned.m8n8.x4.shared.b16 {%0,%1,%2,%3}, [%4];"
                 : "=r"(r[0]), "=r"(r[1]), "=r"(r[2]), "=r"(r[3]) : "r"(addr));
}
DEVINL void mma_f16(float c[4], const uint32_t a[4], const uint32_t b[2]) {
    asm volatile(
        "mma.sync.aligned.m16n8k16.row.col.f32.f16.f16.f32 "
        "{%0,%1,%2,%3}, {%4,%5,%6,%7}, {%8,%9}, {%0,%1,%2,%3};"
        : "+f"(c[0]), "+f"(c[1]), "+f"(c[2]), "+f"(c[3])
        : "r"(a[0]), "r"(a[1]), "r"(a[2]), "r"(a[3]), "r"(b[0]), "r"(b[1]));
}
DEVINL uint32_t pack_h2(float lo, float hi) {
    __half2 h = __floats2half2_rn(lo, hi);
    return *reinterpret_cast<uint32_t*>(&h);
}

// ================= K0: fused preprocessing, one launch =================
// Block ranges: [0, ENC_B) enc->fp16 | [.., +WH_B) Wh->fp16 | [.., +WS_B) ws GEMV | [.., +Z_B) zero ctx
constexpr int ENC_B = (int)((size_t)M_TOTAL * Hh / 2048);  // 32768 blocks, 2048 elems each
constexpr int WH_B  = Hh * Hh / 1024;                      // 1024 blocks, 1024 elems each
constexpr int WS_B  = 256;                                 // 32 b x 8 o-chunks
constexpr int Z_B   = Bb * Hh / 256;                       // 128
constexpr int PRE_BLOCKS = ENC_B + WH_B + WS_B + Z_B;      // 34176

__global__ __launch_bounds__(256) void preprocess_kernel(
    const float* __restrict__ enc, const float* __restrict__ Wh,
    const float* __restrict__ dec, const float* __restrict__ Wsm,
    float* __restrict__ ctx) {
    __shared__ float dec_s[Hh];
    const int bx = blockIdx.x, tid = threadIdx.x;

    if (bx < ENC_B) {
        // enc -> fp16, 8 elements/thread
        size_t i = ((size_t)bx * 256 + tid) * 8;
        float4 v0 = *reinterpret_cast<const float4*>(enc + i);
        float4 v1 = *reinterpret_cast<const float4*>(enc + i + 4);
        uint4 u;
        u.x = pack_h2(v0.x, v0.y); u.y = pack_h2(v0.z, v0.w);
        u.z = pack_h2(v1.x, v1.y); u.w = pack_h2(v1.z, v1.w);
        *reinterpret_cast<uint4*>(g_enc_h + i) = u;
    } else if (bx < ENC_B + WH_B) {
        // Wh -> fp16, 4 elements/thread
        int i = ((bx - ENC_B) * 256 + tid) * 4;
        float4 v = *reinterpret_cast<const float4*>(Wh + i);
        uint2 u;
        u.x = pack_h2(v.x, v.y);
        u.y = pack_h2(v.z, v.w);
        *reinterpret_cast<uint2*>(g_wh_h + i) = u;
    } else if (bx < ENC_B + WH_B + WS_B) {
        // ws[b, oc*128 .. +128) = W_s rows . dec[b]
        int bw = bx - (ENC_B + WH_B);
        int b = bw >> 3, oc = bw & 7;
        int w = tid >> 5, lane = tid & 31;
        *reinterpret_cast<float4*>(&dec_s[tid * 4]) =
            *reinterpret_cast<const float4*>(dec + (size_t)b * Hh + tid * 4);
        __syncthreads();
#pragma unroll 1
        for (int j = 0; j < 16; j++) {
            int o = oc * 128 + w * 16 + j;
            const float* wr = Wsm + (size_t)o * Hh;
            float acc = 0.f;
#pragma unroll
            for (int i = 0; i < 8; i++) {
                int k = (i * 32 + lane) * 4;
                float4 w4 = *reinterpret_cast<const float4*>(wr + k);
                acc += dec_s[k] * w4.x + dec_s[k + 1] * w4.y
                     + dec_s[k + 2] * w4.z + dec_s[k + 3] * w4.w;
            }
#pragma unroll
            for (int off = 16; off; off >>= 1) acc += __shfl_xor_sync(0xffffffffu, acc, off);
            if (lane == 0) g_ws[b * Hh + o] = acc;
        }
    } else {
        // zero ctx (out poisoned by harness)
        int bz = bx - (ENC_B + WH_B + WS_B);
        ctx[bz * 256 + tid] = 0.f;
    }
}

// ================= K1: fused fp16 GEMM + tanh + v-dot -> partial scores =================
// 512 threads, 16 warps in 4(m) x 4(n) grid; warp tile 32(M) x 64(N); BK=64, single sync/step.
// (R6 config: measured 468 us, tensor 53%.)
__global__ __launch_bounds__(NTHREADS, 1) void attn_scores_kernel(const float* __restrict__ vvec) {
    extern __shared__ char smraw[];
    SmemK1& sm = *reinterpret_cast<SmemK1*>(smraw);

    const int tid = threadIdx.x, wid = tid >> 5, lane = tid & 31;
    const int g = lane >> 2, t = lane & 3;
    const int wm = (wid >> 2) * 32;       // 4 m-groups of 32 rows
    const int wn = (wid & 3) * 64;        // 4 n-groups of 64 cols
    const int m_base = blockIdx.y * BM;
    const int n_base = blockIdx.x * BN;
    const int b = m_base >> 11;

    for (int i = tid; i < BN; i += NTHREADS) {
        sm.ws[i] = g_ws[b * Hh + n_base + i];
        sm.v[i]  = vvec[n_base + i];
    }
    if (tid < BM) sm.rowsum[tid] = 0.f;

    // cp.async chunk coordinates: 16B chunks, 8 per 128B k-row (BK=64 halves)
    const int rA = tid >> 3, cA = tid & 7;     // rows 0..63 (+64), chunk col 0..7
    const __half* srcA = g_enc_h + (size_t)(m_base + rA) * Hh + cA * 8;
    const __half* srcB = g_wh_h  + (size_t)(n_base + rA) * Hh + cA * 8;

    auto issue_stage = [&](int stage, int k0) {
#pragma unroll
        for (int i = 0; i < 2; i++)   // A rows rA, rA+64
            cp_async16(smem_u32(reinterpret_cast<char*>(&sm.A[stage][rA + i * 64][0]) + cA * 16),
                       srcA + (size_t)(i * 64) * Hh + k0);
#pragma unroll
        for (int i = 0; i < 4; i++)   // B rows rA, rA+64, rA+128, rA+192
            cp_async16(smem_u32(reinterpret_cast<char*>(&sm.B[stage][rA + i * 64][0]) + cA * 16),
                       srcB + (size_t)(i * 64) * Hh + k0);
        cp_commit();
    };

    float acc[2][8][4];
#pragma unroll
    for (int ma = 0; ma < 2; ma++)
#pragma unroll
        for (int na = 0; na < 8; na++)
#pragma unroll
            for (int r = 0; r < 4; r++) acc[ma][na][r] = 0.f;

    // ldmatrix lane offset (row stride 144B: 8 rows cover distinct 16B spans mod 128B)
    const int lr = lane & 7, sel = lane >> 3;
    const uint32_t lane_off = (uint32_t)((lr + (sel & 1) * 8) * (LDH * 2) + (sel >> 1) * 16);
    const uint32_t baseA = smem_u32(&sm.A[0][0][0]);
    const uint32_t baseB = smem_u32(&sm.B[0][0][0]);
    constexpr uint32_t A_STRIDE = BM * LDH * 2;   // bytes per stage
    constexpr uint32_t B_STRIDE = BN * LDH * 2;

    // prologue: fill stages 0,1
    issue_stage(0, 0);
    issue_stage(1, BK);

    int p = 0;
#pragma unroll 1
    for (int s = 0; s < NSTEPS; s++) {
        cp_wait1();          // stage s complete (<=1 group in flight)
        __syncthreads();     // visible to all; also: all reads of buffer (s-1) finished

        if (s + 2 < NSTEPS) {
            int nxt = p + 2; if (nxt >= PIPE) nxt -= PIPE;
            issue_stage(nxt, (s + 2) * BK);   // overwrites buffer (s-1): safe after sync
        } else {
            cp_commit();                      // empty group keeps accounting uniform
        }

        uint32_t aw = baseA + p * A_STRIDE + (uint32_t)(wm * (LDH * 2)) + lane_off;
        uint32_t bw = baseB + p * B_STRIDE + (uint32_t)(wn * (LDH * 2)) + lane_off;
#pragma unroll
        for (int ka = 0; ka < 4; ka++) {      // 4 x k16 per stage
            uint32_t af[2][4];
#pragma unroll
            for (int ma = 0; ma < 2; ma++)
                ldmatrix_x4(af[ma], aw + (uint32_t)(ma * 16 * (LDH * 2)) + ka * 32);
            uint32_t bf[8][2];
#pragma unroll
            for (int nb = 0; nb < 4; nb++) {
                uint32_t r[4];
                ldmatrix_x4(r, bw + (uint32_t)(nb * 16 * (LDH * 2)) + ka * 32);
                bf[2 * nb][0] = r[0]; bf[2 * nb + 1][0] = r[1];
                bf[2 * nb][1] = r[2]; bf[2 * nb + 1][1] = r[3];
            }
#pragma unroll
            for (int ma = 0; ma < 2; ma++)
#pragma unroll
                for (int na = 0; na < 8; na++)
                    mma_f16(acc[ma][na], af[ma], bf[na]);
        }

        if (++p >= PIPE) p = 0;
    }

    // epilogue: tanh(acc + ws)*v, reduce over n
#pragma unroll
    for (int ma = 0; ma < 2; ma++) {
        float r0 = 0.f, r1 = 0.f;
#pragma unroll
        for (int na = 0; na < 8; na++) {
            int nl = wn + na * 8 + 2 * t;
            float w0 = sm.ws[nl], w1 = sm.ws[nl + 1];
            float v0 = sm.v[nl],  v1 = sm.v[nl + 1];
            r0 += tanh_fast(acc[ma][na][0] + w0) * v0 + tanh_fast(acc[ma][na][1] + w1) * v1;
            r1 += tanh_fast(acc[ma][na][2] + w0) * v0 + tanh_fast(acc[ma][na][3] + w1) * v1;
        }
        r0 += __shfl_xor_sync(0xffffffffu, r0, 1);
        r0 += __shfl_xor_sync(0xffffffffu, r0, 2);
        r1 += __shfl_xor_sync(0xffffffffu, r1, 1);
        r1 += __shfl_xor_sync(0xffffffffu, r1, 2);
        if (t == 0) {
            atomicAdd(&sm.rowsum[wm + ma * 16 + g], r0);
            atomicAdd(&sm.rowsum[wm + ma * 16 + g + 8], r1);
        }
    }
    __syncthreads();
    if (tid < BM) g_part[blockIdx.x][m_base + tid] = sm.rowsum[tid];
}

// ================= K2: softmax over S per batch =================
__global__ void softmax_kernel(float* __restrict__ wout) {
    __shared__ float sc[Ss];
    __shared__ float red[256];
    int b = blockIdx.x, tid = threadIdx.x;
    float mx = -1e30f;
    for (int i = tid; i < Ss; i += 256) {
        int idx = b * Ss + i;
        float v = g_part[0][idx] + g_part[1][idx] + g_part[2][idx] + g_part[3][idx];
        sc[i] = v;
        mx = fmaxf(mx, v);
    }
    red[tid] = mx; __syncthreads();
    for (int o = 128; o; o >>= 1) { if (tid < o) red[tid] = fmaxf(red[tid], red[tid + o]); __syncthreads(); }
    mx = red[0]; __syncthreads();
    float sum = 0.f;
    for (int i = tid; i < Ss; i += 256) { float e = __expf(sc[i] - mx); sc[i] = e; sum += e; }
    red[tid] = sum; __syncthreads();
    for (int o = 128; o; o >>= 1) { if (tid < o) red[tid] += red[tid + o]; __syncthreads(); }
    float inv = 1.f / red[0];
    for (int i = tid; i < Ss; i += 256) wout[b * Ss + i] = sc[i] * inv;
}

// ================= K3: context, s-split x4 with atomicAdd (fp16 enc; ctx pre-zeroed) =================
__global__ void context_kernel(const float* __restrict__ w, float* __restrict__ out) {
    __shared__ float wsh[512];
    int b = blockIdx.y;
    int s0 = blockIdx.z * 512;
    int h2 = blockIdx.x * 256 + threadIdx.x;   // half2 column index, 0..511
    for (int i = threadIdx.x; i < 512; i += 256) wsh[i] = w[b * Ss + s0 + i];
    __syncthreads();
    const __half2* e = reinterpret_cast<const __half2*>(g_enc_h)
                     + (size_t)b * Ss * (Hh / 2) + (size_t)s0 * (Hh / 2) + h2;
    float a0 = 0.f, a1 = 0.f, b0 = 0.f, b1 = 0.f;
#pragma unroll 4
    for (int s = 0; s < 512; s += 2) {
        float2 f0 = __half22float2(e[(size_t)s * (Hh / 2)]);
        float2 f1 = __half22float2(e[(size_t)(s + 1) * (Hh / 2)]);
        a0 += wsh[s] * f0.x;     a1 += wsh[s] * f0.y;
        b0 += wsh[s + 1] * f1.x; b1 += wsh[s + 1] * f1.y;
    }
    atomicAdd(&out[b * Hh + 2 * h2],     a0 + b0);
    atomicAdd(&out[b * Hh + 2 * h2 + 1], a1 + b1);
}

// ================= launcher =================
extern "C" void kernel_launch(void* const* d_in, const int* in_sizes, int n_in,
                              void* d_out, int out_size) {
    (void)in_sizes; (void)n_in; (void)out_size;
    const float* dec = (const float*)d_in[0];   // [32,1024]
    const float* enc = (const float*)d_in[1];   // [32,2048,1024]
    const float* Wh  = (const float*)d_in[2];   // [1024,1024]
    const float* Wsm = (const float*)d_in[3];   // [1024,1024]
    const float* v   = (const float*)d_in[4];   // [1024]
    float* out  = (float*)d_out;
    float* ctx  = out;                 // [32,1024]
    float* attw = out + Bb * Hh;       // [32,2048]

    cudaFuncSetAttribute(attn_scores_kernel, cudaFuncAttributeMaxDynamicSharedMemorySize,
                         (int)sizeof(SmemK1));

    preprocess_kernel<<<PRE_BLOCKS, 256>>>(enc, Wh, dec, Wsm, ctx);
    attn_scores_kernel<<<dim3(NT, M_TOTAL / BM), NTHREADS, sizeof(SmemK1)>>>(v);
    softmax_kernel<<<Bb, 256>>>(attw);
    context_kernel<<<dim3(Hh / 512, Bb, 4), 256>>>(attw, ctx);
}

// round 14
// speedup vs baseline: 1.3349x; 1.0105x over previous
#include <cuda_runtime.h>
#include <cuda_fp16.h>
#include <cstdint>

#define DEVINL __device__ __forceinline__

// ---------------- problem sizes ----------------
constexpr int Bb = 32, Ss = 2048, Hh = 1024;
constexpr int M_TOTAL = Bb * Ss;          // 65536
constexpr int BM = 128, BN = 256, BK = 64;   // K-step = 64 elements
constexpr int NSTEPS = Hh / BK;           // 16
constexpr int NT = Hh / BN;               // 4 N-tiles
constexpr int LDH = 72;                   // padded smem row stride in halves (144B)
constexpr int PIPE = 3;                   // cp.async stages
constexpr int NTHREADS = 512;             // 16 warps

// ---------------- scratch (no allocs allowed) ----------------
__device__ float  g_ws[Bb * Hh];          // W_s @ dec
__device__ __half g_wh_h[Hh * Hh];        // fp16 W_h
__device__ __half g_enc_h[(size_t)M_TOTAL * Hh];  // fp16 encoder (128 MB)
__device__ float  g_part[NT][M_TOTAL];    // partial scores per N-tile

struct SmemK1 {
    __half A[PIPE][BM][LDH];   // 3*128*144B = 55,296 B
    __half B[PIPE][BN][LDH];   // 3*256*144B = 110,592 B
    float ws[BN];
    float v[BN];
    float rowsum[BM];
};

// ---------------- helpers ----------------
DEVINL uint32_t smem_u32(const void* p) {
    uint32_t a;
    asm("{ .reg .u64 t; cvta.to.shared.u64 t, %1; cvt.u32.u64 %0, t; }" : "=r"(a) : "l"(p));
    return a;
}
DEVINL float tanh_fast(float x) {
    float r;
    asm("tanh.approx.f32 %0, %1;" : "=f"(r) : "f"(x));
    return r;
}
DEVINL void cp_async16(uint32_t dst, const void* src) {
    asm volatile("cp.async.cg.shared.global [%0], [%1], 16;" :: "r"(dst), "l"(src));
}
DEVINL void cp_commit() { asm volatile("cp.async.commit_group;"); }
DEVINL void cp_wait1()  { asm volatile("cp.async.wait_group 1;"); }

DEVINL void ldmatrix_x4(uint32_t r[4], uint32_t addr) {
    asm volatile("ldmatrix.sync.aligned.m8n8.x4.shared.b16 {%0,%1,%2,%3}, [%4];"
                 : "=r"(r[0]), "=r"(r[1]), "=r"(r[2]), "=r"(r[3]) : "r"(addr));
}
DEVINL void mma_f16(float c[4], const uint32_t a[4], const uint32_t b[2]) {
    asm volatile(
        "mma.sync.aligned.m16n8k16.row.col.f32.f16.f16.f32 "
        "{%0,%1,%2,%3}, {%4,%5,%6,%7}, {%8,%9}, {%0,%1,%2,%3};"
        : "+f"(c[0]), "+f"(c[1]), "+f"(c[2]), "+f"(c[3])
        : "r"(a[0]), "r"(a[1]), "r"(a[2]), "r"(a[3]), "r"(b[0]), "r"(b[1]));
}
DEVINL uint32_t pack_h2(float lo, float hi) {
    __half2 h = __floats2half2_rn(lo, hi);
    return *reinterpret_cast<uint32_t*>(&h);
}

// ================= K0: fused preprocessing, one launch =================
// Block ranges: [0, ENC_B) enc->fp16 | [.., +WH_B) Wh->fp16 | [.., +WS_B) ws GEMV | [.., +Z_B) zero ctx
constexpr int ENC_B = (int)((size_t)M_TOTAL * Hh / 2048);  // 32768 blocks, 2048 elems each
constexpr int WH_B  = Hh * Hh / 1024;                      // 1024 blocks, 1024 elems each
constexpr int WS_B  = 256;                                 // 32 b x 8 o-chunks
constexpr int Z_B   = Bb * Hh / 256;                       // 128
constexpr int PRE_BLOCKS = ENC_B + WH_B + WS_B + Z_B;      // 34176

__global__ __launch_bounds__(256) void preprocess_kernel(
    const float* __restrict__ enc, const float* __restrict__ Wh,
    const float* __restrict__ dec, const float* __restrict__ Wsm,
    float* __restrict__ ctx) {
    __shared__ float dec_s[Hh];
    const int bx = blockIdx.x, tid = threadIdx.x;

    if (bx < ENC_B) {
        // enc -> fp16, 8 elements/thread
        size_t i = ((size_t)bx * 256 + tid) * 8;
        float4 v0 = *reinterpret_cast<const float4*>(enc + i);
        float4 v1 = *reinterpret_cast<const float4*>(enc + i + 4);
        uint4 u;
        u.x = pack_h2(v0.x, v0.y); u.y = pack_h2(v0.z, v0.w);
        u.z = pack_h2(v1.x, v1.y); u.w = pack_h2(v1.z, v1.w);
        *reinterpret_cast<uint4*>(g_enc_h + i) = u;
    } else if (bx < ENC_B + WH_B) {
        // Wh -> fp16, 4 elements/thread
        int i = ((bx - ENC_B) * 256 + tid) * 4;
        float4 v = *reinterpret_cast<const float4*>(Wh + i);
        uint2 u;
        u.x = pack_h2(v.x, v.y);
        u.y = pack_h2(v.z, v.w);
        *reinterpret_cast<uint2*>(g_wh_h + i) = u;
    } else if (bx < ENC_B + WH_B + WS_B) {
        // ws[b, oc*128 .. +128) = W_s rows . dec[b]
        int bw = bx - (ENC_B + WH_B);
        int b = bw >> 3, oc = bw & 7;
        int w = tid >> 5, lane = tid & 31;
        *reinterpret_cast<float4*>(&dec_s[tid * 4]) =
            *reinterpret_cast<const float4*>(dec + (size_t)b * Hh + tid * 4);
        __syncthreads();
#pragma unroll 1
        for (int j = 0; j < 16; j++) {
            int o = oc * 128 + w * 16 + j;
            const float* wr = Wsm + (size_t)o * Hh;
            float acc = 0.f;
#pragma unroll
            for (int i = 0; i < 8; i++) {
                int k = (i * 32 + lane) * 4;
                float4 w4 = *reinterpret_cast<const float4*>(wr + k);
                acc += dec_s[k] * w4.x + dec_s[k + 1] * w4.y
                     + dec_s[k + 2] * w4.z + dec_s[k + 3] * w4.w;
            }
#pragma unroll
            for (int off = 16; off; off >>= 1) acc += __shfl_xor_sync(0xffffffffu, acc, off);
            if (lane == 0) g_ws[b * Hh + o] = acc;
        }
    } else {
        // zero ctx (out poisoned by harness)
        int bz = bx - (ENC_B + WH_B + WS_B);
        ctx[bz * 256 + tid] = 0.f;
    }
}

// ================= K1: fused fp16 GEMM + tanh + v-dot -> partial scores =================
// 512 threads, 16 warps in 4(m) x 4(n) grid; warp tile 32(M) x 64(N); BK=64, single sync/step.
__global__ __launch_bounds__(NTHREADS, 1) void attn_scores_kernel(const float* __restrict__ vvec) {
    extern __shared__ char smraw[];
    SmemK1& sm = *reinterpret_cast<SmemK1*>(smraw);

    const int tid = threadIdx.x, wid = tid >> 5, lane = tid & 31;
    const int g = lane >> 2, t = lane & 3;
    const int wm = (wid >> 2) * 32;       // 4 m-groups of 32 rows
    const int wn = (wid & 3) * 64;        // 4 n-groups of 64 cols
    const int m_base = blockIdx.y * BM;
    const int n_base = blockIdx.x * BN;
    const int b = m_base >> 11;

    for (int i = tid; i < BN; i += NTHREADS) {
        sm.ws[i] = g_ws[b * Hh + n_base + i];
        sm.v[i]  = vvec[n_base + i];
    }
    if (tid < BM) sm.rowsum[tid] = 0.f;

    // cp.async chunk coordinates: 16B chunks, 8 per 128B k-row (BK=64 halves)
    const int rA = tid >> 3, cA = tid & 7;     // rows 0..63 (+64), chunk col 0..7
    const __half* srcA = g_enc_h + (size_t)(m_base + rA) * Hh + cA * 8;
    const __half* srcB = g_wh_h  + (size_t)(n_base + rA) * Hh + cA * 8;

    auto issue_stage = [&](int stage, int k0) {
#pragma unroll
        for (int i = 0; i < 2; i++)   // A rows rA, rA+64
            cp_async16(smem_u32(reinterpret_cast<char*>(&sm.A[stage][rA + i * 64][0]) + cA * 16),
                       srcA + (size_t)(i * 64) * Hh + k0);
#pragma unroll
        for (int i = 0; i < 4; i++)   // B rows rA, rA+64, rA+128, rA+192
            cp_async16(smem_u32(reinterpret_cast<char*>(&sm.B[stage][rA + i * 64][0]) + cA * 16),
                       srcB + (size_t)(i * 64) * Hh + k0);
        cp_commit();
    };

    float acc[2][8][4];
#pragma unroll
    for (int ma = 0; ma < 2; ma++)
#pragma unroll
        for (int na = 0; na < 8; na++)
#pragma unroll
            for (int r = 0; r < 4; r++) acc[ma][na][r] = 0.f;

    // ldmatrix lane offset (row stride 144B: 8 rows cover distinct 16B spans mod 128B)
    const int lr = lane & 7, sel = lane >> 3;
    const uint32_t lane_off = (uint32_t)((lr + (sel & 1) * 8) * (LDH * 2) + (sel >> 1) * 16);
    const uint32_t baseA = smem_u32(&sm.A[0][0][0]);
    const uint32_t baseB = smem_u32(&sm.B[0][0][0]);
    constexpr uint32_t A_STRIDE = BM * LDH * 2;   // bytes per stage
    constexpr uint32_t B_STRIDE = BN * LDH * 2;

    // prologue: fill stages 0,1
    issue_stage(0, 0);
    issue_stage(1, BK);

    int p = 0;
#pragma unroll 1
    for (int s = 0; s < NSTEPS; s++) {
        cp_wait1();          // stage s complete (<=1 group in flight)
        __syncthreads();     // visible to all; also: all reads of buffer (s-1) finished

        if (s + 2 < NSTEPS) {
            int nxt = p + 2; if (nxt >= PIPE) nxt -= PIPE;
            issue_stage(nxt, (s + 2) * BK);   // overwrites buffer (s-1): safe after sync
        } else {
            cp_commit();                      // empty group keeps accounting uniform
        }

        uint32_t aw = baseA + p * A_STRIDE + (uint32_t)(wm * (LDH * 2)) + lane_off;
        uint32_t bw = baseB + p * B_STRIDE + (uint32_t)(wn * (LDH * 2)) + lane_off;
#pragma unroll
        for (int ka = 0; ka < 4; ka++) {      // 4 x k16 per stage
            uint32_t af[2][4];
#pragma unroll
            for (int ma = 0; ma < 2; ma++)
                ldmatrix_x4(af[ma], aw + (uint32_t)(ma * 16 * (LDH * 2)) + ka * 32);
            uint32_t bf[8][2];
#pragma unroll
            for (int nb = 0; nb < 4; nb++) {
                uint32_t r[4];
                ldmatrix_x4(r, bw + (uint32_t)(nb * 16 * (LDH * 2)) + ka * 32);
                bf[2 * nb][0] = r[0]; bf[2 * nb + 1][0] = r[1];
                bf[2 * nb][1] = r[2]; bf[2 * nb + 1][1] = r[3];
            }
#pragma unroll
            for (int ma = 0; ma < 2; ma++)
#pragma unroll
                for (int na = 0; na < 8; na++)
                    mma_f16(acc[ma][na], af[ma], bf[na]);
        }

        if (++p >= PIPE) p = 0;
    }

    // epilogue: tanh(acc + ws)*v, reduce over n
#pragma unroll
    for (int ma = 0; ma < 2; ma++) {
        float r0 = 0.f, r1 = 0.f;
#pragma unroll
        for (int na = 0; na < 8; na++) {
            int nl = wn + na * 8 + 2 * t;
            float w0 = sm.ws[nl], w1 = sm.ws[nl + 1];
            float v0 = sm.v[nl],  v1 = sm.v[nl + 1];
            r0 += tanh_fast(acc[ma][na][0] + w0) * v0 + tanh_fast(acc[ma][na][1] + w1) * v1;
            r1 += tanh_fast(acc[ma][na][2] + w0) * v0 + tanh_fast(acc[ma][na][3] + w1) * v1;
        }
        r0 += __shfl_xor_sync(0xffffffffu, r0, 1);
        r0 += __shfl_xor_sync(0xffffffffu, r0, 2);
        r1 += __shfl_xor_sync(0xffffffffu, r1, 1);
        r1 += __shfl_xor_sync(0xffffffffu, r1, 2);
        if (t == 0) {
            atomicAdd(&sm.rowsum[wm + ma * 16 + g], r0);
            atomicAdd(&sm.rowsum[wm + ma * 16 + g + 8], r1);
        }
    }
    __syncthreads();
    if (tid < BM) g_part[blockIdx.x][m_base + tid] = sm.rowsum[tid];
}

// ================= K2: softmax over S per batch =================
__global__ void softmax_kernel(float* __restrict__ wout) {
    __shared__ float sc[Ss];
    __shared__ float red[256];
    int b = blockIdx.x, tid = threadIdx.x;
    float mx = -1e30f;
    for (int i = tid; i < Ss; i += 256) {
        int idx = b * Ss + i;
        float v = g_part[0][idx] + g_part[1][idx] + g_part[2][idx] + g_part[3][idx];
        sc[i] = v;
        mx = fmaxf(mx, v);
    }
    red[tid] = mx; __syncthreads();
    for (int o = 128; o; o >>= 1) { if (tid < o) red[tid] = fmaxf(red[tid], red[tid + o]); __syncthreads(); }
    mx = red[0]; __syncthreads();
    float sum = 0.f;
    for (int i = tid; i < Ss; i += 256) { float e = __expf(sc[i] - mx); sc[i] = e; sum += e; }
    red[tid] = sum; __syncthreads();
    for (int o = 128; o; o >>= 1) { if (tid < o) red[tid] += red[tid + o]; __syncthreads(); }
    float inv = 1.f / red[0];
    for (int i = tid; i < Ss; i += 256) wout[b * Ss + i] = sc[i] * inv;
}

// ================= K3: context, vectorized 16B loads, s-split x16, atomicAdd =================
// grid (1, Bb, 16), block 256. Thread owns 8 h-columns (one uint4 per s-row).
// tid&127 -> column group; tid>>7 -> s parity. 128 s-rows per block.
__global__ __launch_bounds__(256) void context_kernel(const float* __restrict__ w,
                                                      float* __restrict__ out) {
    __shared__ float wsh[128];
    const int b = blockIdx.y;
    const int s0 = blockIdx.z * 128;
    const int tid = threadIdx.x;
    const int h8 = tid & 127;          // column group: halves [h8*8, h8*8+8)
    const int sp = tid >> 7;           // s parity 0/1
    if (tid < 128) wsh[tid] = w[b * Ss + s0 + tid];
    __syncthreads();

    const uint4* e = reinterpret_cast<const uint4*>(g_enc_h + (size_t)(b * Ss + s0) * Hh) + h8;
    constexpr int ROW_U4 = Hh / 8;     // 128 uint4 per s-row

    float acc[8];
#pragma unroll
    for (int j = 0; j < 8; j++) acc[j] = 0.f;

#pragma unroll 4
    for (int s = sp; s < 128; s += 2) {
        uint4 u = e[(size_t)s * ROW_U4];
        float wgt = wsh[s];
        float2 f0 = __half22float2(*reinterpret_cast<__half2*>(&u.x));
        float2 f1 = __half22float2(*reinterpret_cast<__half2*>(&u.y));
        float2 f2 = __half22float2(*reinterpret_cast<__half2*>(&u.z));
        float2 f3 = __half22float2(*reinterpret_cast<__half2*>(&u.w));
        acc[0] += wgt * f0.x; acc[1] += wgt * f0.y;
        acc[2] += wgt * f1.x; acc[3] += wgt * f1.y;
        acc[4] += wgt * f2.x; acc[5] += wgt * f2.y;
        acc[6] += wgt * f3.x; acc[7] += wgt * f3.y;
    }

    float* dst = out + b * Hh + h8 * 8;
#pragma unroll
    for (int j = 0; j < 8; j++) atomicAdd(&dst[j], acc[j]);
}

// ================= launcher =================
extern "C" void kernel_launch(void* const* d_in, const int* in_sizes, int n_in,
                              void* d_out, int out_size) {
    (void)in_sizes; (void)n_in; (void)out_size;
    const float* dec = (const float*)d_in[0];   // [32,1024]
    const float* enc = (const float*)d_in[1];   // [32,2048,1024]
    const float* Wh  = (const float*)d_in[2];   // [1024,1024]
    const float* Wsm = (const float*)d_in[3];   // [1024,1024]
    const float* v   = (const float*)d_in[4];   // [1024]
    float* out  = (float*)d_out;
    float* ctx  = out;                 // [32,1024]
    float* attw = out + Bb * Hh;       // [32,2048]

    cudaFuncSetAttribute(attn_scores_kernel, cudaFuncAttributeMaxDynamicSharedMemorySize,
                         (int)sizeof(SmemK1));

    preprocess_kernel<<<PRE_BLOCKS, 256>>>(enc, Wh, dec, Wsm, ctx);
    attn_scores_kernel<<<dim3(NT, M_TOTAL / BM), NTHREADS, sizeof(SmemK1)>>>(v);
    softmax_kernel<<<Bb, 256>>>(attw);
    context_kernel<<<dim3(1, Bb, 16), 256>>>(attw, ctx);
}

// round 15
// speedup vs baseline: 1.3350x; 1.0001x over previous
#include <cuda_runtime.h>
#include <cuda_fp16.h>
#include <cstdint>

#define DEVINL __device__ __forceinline__

// ---------------- problem sizes ----------------
constexpr int Bb = 32, Ss = 2048, Hh = 1024;
constexpr int M_TOTAL = Bb * Ss;          // 65536
constexpr int BM = 128, BN = 256, BK = 64;   // K-step = 64 elements
constexpr int NSTEPS = Hh / BK;           // 16
constexpr int NT = Hh / BN;               // 4 N-tiles
constexpr int LDH = 72;                   // padded smem row stride in halves (144B)
constexpr int PIPE = 3;                   // cp.async stages
constexpr int NTHREADS = 512;             // 16 warps

// ---------------- scratch (no allocs allowed) ----------------
__device__ float  g_ws[Bb * Hh];          // W_s @ dec
__device__ __half g_wh_h[Hh * Hh];        // fp16 W_h
__device__ __half g_enc_h[(size_t)M_TOTAL * Hh];  // fp16 encoder (128 MB)
__device__ float  g_part[NT][M_TOTAL];    // partial scores per N-tile

struct SmemK1 {
    __half A[PIPE][BM][LDH];   // 3*128*144B = 55,296 B
    __half B[PIPE][BN][LDH];   // 3*256*144B = 110,592 B
    float ws[BN];
    float v[BN];
    float rowsum[BM];
};

// ---------------- helpers ----------------
DEVINL uint32_t smem_u32(const void* p) {
    uint32_t a;
    asm("{ .reg .u64 t; cvta.to.shared.u64 t, %1; cvt.u32.u64 %0, t; }" : "=r"(a) : "l"(p));
    return a;
}
DEVINL float tanh_fast(float x) {
    float r;
    asm("tanh.approx.f32 %0, %1;" : "=f"(r) : "f"(x));
    return r;
}
DEVINL void cp_async16(uint32_t dst, const void* src) {
    asm volatile("cp.async.cg.shared.global [%0], [%1], 16;" :: "r"(dst), "l"(src));
}
DEVINL void cp_commit() { asm volatile("cp.async.commit_group;"); }
DEVINL void cp_wait1()  { asm volatile("cp.async.wait_group 1;"); }

DEVINL void ldmatrix_x4(uint32_t r[4], uint32_t addr) {
    asm volatile("ldmatrix.sync.aligned.m8n8.x4.shared.b16 {%0,%1,%2,%3}, [%4];"
                 : "=r"(r[0]), "=r"(r[1]), "=r"(r[2]), "=r"(r[3]) : "r"(addr));
}
DEVINL void mma_f16(float c[4], const uint32_t a[4], const uint32_t b[2]) {
    asm volatile(
        "mma.sync.aligned.m16n8k16.row.col.f32.f16.f16.f32 "
        "{%0,%1,%2,%3}, {%4,%5,%6,%7}, {%8,%9}, {%0,%1,%2,%3};"
        : "+f"(c[0]), "+f"(c[1]), "+f"(c[2]), "+f"(c[3])
        : "r"(a[0]), "r"(a[1]), "r"(a[2]), "r"(a[3]), "r"(b[0]), "r"(b[1]));
}
DEVINL uint32_t pack_h2(float lo, float hi) {
    __half2 h = __floats2half2_rn(lo, hi);
    return *reinterpret_cast<uint32_t*>(&h);
}

// ================= K0: fused preprocessing, one launch =================
// Block ranges: [0, ENC_B) enc->fp16 | [.., +WH_B) Wh->fp16 | [.., +WS_B) ws GEMV | [.., +Z_B) zero ctx
constexpr int ENC_B = (int)((size_t)M_TOTAL * Hh / 2048);  // 32768 blocks, 2048 elems each
constexpr int WH_B  = Hh * Hh / 1024;                      // 1024 blocks, 1024 elems each
constexpr int WS_B  = 256;                                 // 32 b x 8 o-chunks
constexpr int Z_B   = Bb * Hh / 256;                       // 128
constexpr int PRE_BLOCKS = ENC_B + WH_B + WS_B + Z_B;      // 34176

__global__ __launch_bounds__(256) void preprocess_kernel(
    const float* __restrict__ enc, const float* __restrict__ Wh,
    const float* __restrict__ dec, const float* __restrict__ Wsm,
    float* __restrict__ ctx) {
    __shared__ float dec_s[Hh];
    const int bx = blockIdx.x, tid = threadIdx.x;

    if (bx < ENC_B) {
        // enc -> fp16, 8 elements/thread
        size_t i = ((size_t)bx * 256 + tid) * 8;
        float4 v0 = *reinterpret_cast<const float4*>(enc + i);
        float4 v1 = *reinterpret_cast<const float4*>(enc + i + 4);
        uint4 u;
        u.x = pack_h2(v0.x, v0.y); u.y = pack_h2(v0.z, v0.w);
        u.z = pack_h2(v1.x, v1.y); u.w = pack_h2(v1.z, v1.w);
        *reinterpret_cast<uint4*>(g_enc_h + i) = u;
    } else if (bx < ENC_B + WH_B) {
        // Wh -> fp16, 4 elements/thread
        int i = ((bx - ENC_B) * 256 + tid) * 4;
        float4 v = *reinterpret_cast<const float4*>(Wh + i);
        uint2 u;
        u.x = pack_h2(v.x, v.y);
        u.y = pack_h2(v.z, v.w);
        *reinterpret_cast<uint2*>(g_wh_h + i) = u;
    } else if (bx < ENC_B + WH_B + WS_B) {
        // ws[b, oc*128 .. +128) = W_s rows . dec[b]
        int bw = bx - (ENC_B + WH_B);
        int b = bw >> 3, oc = bw & 7;
        int w = tid >> 5, lane = tid & 31;
        *reinterpret_cast<float4*>(&dec_s[tid * 4]) =
            *reinterpret_cast<const float4*>(dec + (size_t)b * Hh + tid * 4);
        __syncthreads();
#pragma unroll 1
        for (int j = 0; j < 16; j++) {
            int o = oc * 128 + w * 16 + j;
            const float* wr = Wsm + (size_t)o * Hh;
            float acc = 0.f;
#pragma unroll
            for (int i = 0; i < 8; i++) {
                int k = (i * 32 + lane) * 4;
                float4 w4 = *reinterpret_cast<const float4*>(wr + k);
                acc += dec_s[k] * w4.x + dec_s[k + 1] * w4.y
                     + dec_s[k + 2] * w4.z + dec_s[k + 3] * w4.w;
            }
#pragma unroll
            for (int off = 16; off; off >>= 1) acc += __shfl_xor_sync(0xffffffffu, acc, off);
            if (lane == 0) g_ws[b * Hh + o] = acc;
        }
    } else {
        // zero ctx (out poisoned by harness)
        int bz = bx - (ENC_B + WH_B + WS_B);
        ctx[bz * 256 + tid] = 0.f;
    }
}

// ================= K1: fused fp16 GEMM + tanh + v-dot -> partial scores =================
// 512 threads, 16 warps in 4(m) x 4(n) grid; warp tile 32(M) x 64(N); BK=64, single sync/step.
__global__ __launch_bounds__(NTHREADS, 1) void attn_scores_kernel(const float* __restrict__ vvec) {
    extern __shared__ char smraw[];
    SmemK1& sm = *reinterpret_cast<SmemK1*>(smraw);

    const int tid = threadIdx.x, wid = tid >> 5, lane = tid & 31;
    const int g = lane >> 2, t = lane & 3;
    const int wm = (wid >> 2) * 32;       // 4 m-groups of 32 rows
    const int wn = (wid & 3) * 64;        // 4 n-groups of 64 cols
    const int m_base = blockIdx.y * BM;
    const int n_base = blockIdx.x * BN;
    const int b = m_base >> 11;

    for (int i = tid; i < BN; i += NTHREADS) {
        sm.ws[i] = g_ws[b * Hh + n_base + i];
        sm.v[i]  = vvec[n_base + i];
    }
    if (tid < BM) sm.rowsum[tid] = 0.f;

    // cp.async chunk coordinates: 16B chunks, 8 per 128B k-row (BK=64 halves)
    const int rA = tid >> 3, cA = tid & 7;     // rows 0..63 (+64), chunk col 0..7
    const __half* srcA = g_enc_h + (size_t)(m_base + rA) * Hh + cA * 8;
    const __half* srcB = g_wh_h  + (size_t)(n_base + rA) * Hh + cA * 8;

    auto issue_stage = [&](int stage, int k0) {
#pragma unroll
        for (int i = 0; i < 2; i++)   // A rows rA, rA+64
            cp_async16(smem_u32(reinterpret_cast<char*>(&sm.A[stage][rA + i * 64][0]) + cA * 16),
                       srcA + (size_t)(i * 64) * Hh + k0);
#pragma unroll
        for (int i = 0; i < 4; i++)   // B rows rA, rA+64, rA+128, rA+192
            cp_async16(smem_u32(reinterpret_cast<char*>(&sm.B[stage][rA + i * 64][0]) + cA * 16),
                       srcB + (size_t)(i * 64) * Hh + k0);
        cp_commit();
    };

    float acc[2][8][4];
#pragma unroll
    for (int ma = 0; ma < 2; ma++)
#pragma unroll
        for (int na = 0; na < 8; na++)
#pragma unroll
            for (int r = 0; r < 4; r++) acc[ma][na][r] = 0.f;

    // ldmatrix lane offset (row stride 144B: 8 rows cover distinct 16B spans mod 128B)
    const int lr = lane & 7, sel = lane >> 3;
    const uint32_t lane_off = (uint32_t)((lr + (sel & 1) * 8) * (LDH * 2) + (sel >> 1) * 16);
    const uint32_t baseA = smem_u32(&sm.A[0][0][0]);
    const uint32_t baseB = smem_u32(&sm.B[0][0][0]);
    constexpr uint32_t A_STRIDE = BM * LDH * 2;   // bytes per stage
    constexpr uint32_t B_STRIDE = BN * LDH * 2;

    // prologue: fill stages 0,1
    issue_stage(0, 0);
    issue_stage(1, BK);

    int p = 0;
#pragma unroll 1
    for (int s = 0; s < NSTEPS; s++) {
        cp_wait1();          // stage s complete (<=1 group in flight)
        __syncthreads();     // visible to all; also: all reads of buffer (s-1) finished

        if (s + 2 < NSTEPS) {
            int nxt = p + 2; if (nxt >= PIPE) nxt -= PIPE;
            issue_stage(nxt, (s + 2) * BK);   // overwrites buffer (s-1): safe after sync
        } else {
            cp_commit();                      // empty group keeps accounting uniform
        }

        uint32_t aw = baseA + p * A_STRIDE + (uint32_t)(wm * (LDH * 2)) + lane_off;
        uint32_t bw = baseB + p * B_STRIDE + (uint32_t)(wn * (LDH * 2)) + lane_off;
#pragma unroll
        for (int ka = 0; ka < 4; ka++) {      // 4 x k16 per stage
            uint32_t af[2][4];
#pragma unroll
            for (int ma = 0; ma < 2; ma++)
                ldmatrix_x4(af[ma], aw + (uint32_t)(ma * 16 * (LDH * 2)) + ka * 32);
            uint32_t bf[8][2];
#pragma unroll
            for (int nb = 0; nb < 4; nb++) {
                uint32_t r[4];
                ldmatrix_x4(r, bw + (uint32_t)(nb * 16 * (LDH * 2)) + ka * 32);
                bf[2 * nb][0] = r[0]; bf[2 * nb + 1][0] = r[1];
                bf[2 * nb][1] = r[2]; bf[2 * nb + 1][1] = r[3];
            }
#pragma unroll
            for (int ma = 0; ma < 2; ma++)
#pragma unroll
                for (int na = 0; na < 8; na++)
                    mma_f16(acc[ma][na], af[ma], bf[na]);
        }

        if (++p >= PIPE) p = 0;
    }

    // epilogue: tanh(acc + ws)*v, reduce over n
#pragma unroll
    for (int ma = 0; ma < 2; ma++) {
        float r0 = 0.f, r1 = 0.f;
#pragma unroll
        for (int na = 0; na < 8; na++) {
            int nl = wn + na * 8 + 2 * t;
            float w0 = sm.ws[nl], w1 = sm.ws[nl + 1];
            float v0 = sm.v[nl],  v1 = sm.v[nl + 1];
            r0 += tanh_fast(acc[ma][na][0] + w0) * v0 + tanh_fast(acc[ma][na][1] + w1) * v1;
            r1 += tanh_fast(acc[ma][na][2] + w0) * v0 + tanh_fast(acc[ma][na][3] + w1) * v1;
        }
        r0 += __shfl_xor_sync(0xffffffffu, r0, 1);
        r0 += __shfl_xor_sync(0xffffffffu, r0, 2);
        r1 += __shfl_xor_sync(0xffffffffu, r1, 1);
        r1 += __shfl_xor_sync(0xffffffffu, r1, 2);
        if (t == 0) {
            atomicAdd(&sm.rowsum[wm + ma * 16 + g], r0);
            atomicAdd(&sm.rowsum[wm + ma * 16 + g + 8], r1);
        }
    }
    __syncthreads();
    if (tid < BM) g_part[blockIdx.x][m_base + tid] = sm.rowsum[tid];
}

// ================= K2: softmax over S per batch =================
__global__ void softmax_kernel(float* __restrict__ wout) {
    __shared__ float sc[Ss];
    __shared__ float red[256];
    int b = blockIdx.x, tid = threadIdx.x;
    float mx = -1e30f;
    for (int i = tid; i < Ss; i += 256) {
        int idx = b * Ss + i;
        float v = g_part[0][idx] + g_part[1][idx] + g_part[2][idx] + g_part[3][idx];
        sc[i] = v;
        mx = fmaxf(mx, v);
    }
    red[tid] = mx; __syncthreads();
    for (int o = 128; o; o >>= 1) { if (tid < o) red[tid] = fmaxf(red[tid], red[tid + o]); __syncthreads(); }
    mx = red[0]; __syncthreads();
    float sum = 0.f;
    for (int i = tid; i < Ss; i += 256) { float e = __expf(sc[i] - mx); sc[i] = e; sum += e; }
    red[tid] = sum; __syncthreads();
    for (int o = 128; o; o >>= 1) { if (tid < o) red[tid] += red[tid + o]; __syncthreads(); }
    float inv = 1.f / red[0];
    for (int i = tid; i < Ss; i += 256) wout[b * Ss + i] = sc[i] * inv;
}

// ================= K3: context, 16B loads, s-split x32, unroll 8, atomicAdd =================
// grid (1, Bb, 32), block 256. Thread owns 8 h-columns (one uint4 per s-row); 64 s-rows/block.
__global__ __launch_bounds__(256) void context_kernel(const float* __restrict__ w,
                                                      float* __restrict__ out) {
    __shared__ float wsh[64];
    const int b = blockIdx.y;
    const int s0 = blockIdx.z * 64;
    const int tid = threadIdx.x;
    const int h8 = tid & 127;          // column group: halves [h8*8, h8*8+8)
    const int sp = tid >> 7;           // s parity 0/1
    if (tid < 64) wsh[tid] = w[b * Ss + s0 + tid];
    __syncthreads();

    const uint4* e = reinterpret_cast<const uint4*>(g_enc_h + (size_t)(b * Ss + s0) * Hh) + h8;
    constexpr int ROW_U4 = Hh / 8;     // 128 uint4 per s-row

    float acc[8];
#pragma unroll
    for (int j = 0; j < 8; j++) acc[j] = 0.f;

#pragma unroll 8
    for (int s = sp; s < 64; s += 2) {
        uint4 u = e[(size_t)s * ROW_U4];
        float wgt = wsh[s];
        float2 f0 = __half22float2(*reinterpret_cast<__half2*>(&u.x));
        float2 f1 = __half22float2(*reinterpret_cast<__half2*>(&u.y));
        float2 f2 = __half22float2(*reinterpret_cast<__half2*>(&u.z));
        float2 f3 = __half22float2(*reinterpret_cast<__half2*>(&u.w));
        acc[0] += wgt * f0.x; acc[1] += wgt * f0.y;
        acc[2] += wgt * f1.x; acc[3] += wgt * f1.y;
        acc[4] += wgt * f2.x; acc[5] += wgt * f2.y;
        acc[6] += wgt * f3.x; acc[7] += wgt * f3.y;
    }

    float* dst = out + b * Hh + h8 * 8;
#pragma unroll
    for (int j = 0; j < 8; j++) atomicAdd(&dst[j], acc[j]);
}

// ================= launcher =================
extern "C" void kernel_launch(void* const* d_in, const int* in_sizes, int n_in,
                              void* d_out, int out_size) {
    (void)in_sizes; (void)n_in; (void)out_size;
    const float* dec = (const float*)d_in[0];   // [32,1024]
    const float* enc = (const float*)d_in[1];   // [32,2048,1024]
    const float* Wh  = (const float*)d_in[2];   // [1024,1024]
    const float* Wsm = (const float*)d_in[3];   // [1024,1024]
    const float* v   = (const float*)d_in[4];   // [1024]
    float* out  = (float*)d_out;
    float* ctx  = out;                 // [32,1024]
    float* attw = out + Bb * Hh;       // [32,2048]

    cudaFuncSetAttribute(attn_scores_kernel, cudaFuncAttributeMaxDynamicSharedMemorySize,
                         (int)sizeof(SmemK1));

    preprocess_kernel<<<PRE_BLOCKS, 256>>>(enc, Wh, dec, Wsm, ctx);
    attn_scores_kernel<<<dim3(NT, M_TOTAL / BM), NTHREADS, sizeof(SmemK1)>>>(v);
    softmax_kernel<<<Bb, 256>>>(attw);
    context_kernel<<<dim3(1, Bb, 32), 256>>>(attw, ctx);
}

// round 16
// speedup vs baseline: 1.3487x; 1.0103x over previous
#include <cuda_runtime.h>
#include <cuda_fp16.h>
#include <cstdint>

#define DEVINL __device__ __forceinline__

// ---------------- problem sizes ----------------
constexpr int Bb = 32, Ss = 2048, Hh = 1024;
constexpr int M_TOTAL = Bb * Ss;          // 65536
constexpr int BM = 128, BN = 256, BK = 64;   // K-step = 64 elements
constexpr int NSTEPS = Hh / BK;           // 16
constexpr int NT = Hh / BN;               // 4 N-tiles
constexpr int LDH = 72;                   // padded smem row stride in halves (144B)
constexpr int PIPE = 3;                   // cp.async stages
constexpr int NTHREADS = 512;             // 16 warps

// ---------------- scratch (no allocs allowed) ----------------
__device__ float  g_ws[Bb * Hh];          // W_s @ dec
__device__ __half g_wh_h[Hh * Hh];        // fp16 W_h
__device__ __half g_enc_h[(size_t)M_TOTAL * Hh];  // fp16 encoder (128 MB)
__device__ float  g_part[NT][M_TOTAL];    // partial scores per N-tile

struct SmemK1 {
    __half A[PIPE][BM][LDH];   // 3*128*144B = 55,296 B
    __half B[PIPE][BN][LDH];   // 3*256*144B = 110,592 B
    float ws[BN];
    float v[BN];
    float rowsum[BM];
};

// ---------------- helpers ----------------
DEVINL uint32_t smem_u32(const void* p) {
    uint32_t a;
    asm("{ .reg .u64 t; cvta.to.shared.u64 t, %1; cvt.u32.u64 %0, t; }" : "=r"(a) : "l"(p));
    return a;
}
DEVINL float tanh_fast(float x) {
    float r;
    asm("tanh.approx.f32 %0, %1;" : "=f"(r) : "f"(x));
    return r;
}
DEVINL void cp_async16(uint32_t dst, const void* src) {
    asm volatile("cp.async.cg.shared.global [%0], [%1], 16;" :: "r"(dst), "l"(src));
}
DEVINL void cp_commit() { asm volatile("cp.async.commit_group;"); }
DEVINL void cp_wait1()  { asm volatile("cp.async.wait_group 1;"); }

DEVINL void ldmatrix_x4(uint32_t r[4], uint32_t addr) {
    asm volatile("ldmatrix.sync.aligned.m8n8.x4.shared.b16 {%0,%1,%2,%3}, [%4];"
                 : "=r"(r[0]), "=r"(r[1]), "=r"(r[2]), "=r"(r[3]) : "r"(addr));
}
DEVINL void mma_f16(float c[4], const uint32_t a[4], const uint32_t b[2]) {
    asm volatile(
        "mma.sync.aligned.m16n8k16.row.col.f32.f16.f16.f32 "
        "{%0,%1,%2,%3}, {%4,%5,%6,%7}, {%8,%9}, {%0,%1,%2,%3};"
        : "+f"(c[0]), "+f"(c[1]), "+f"(c[2]), "+f"(c[3])
        : "r"(a[0]), "r"(a[1]), "r"(a[2]), "r"(a[3]), "r"(b[0]), "r"(b[1]));
}
DEVINL uint32_t pack_h2(float lo, float hi) {
    __half2 h = __floats2half2_rn(lo, hi);
    return *reinterpret_cast<uint32_t*>(&h);
}

// ================= K0: fused preprocessing, one launch =================
// Block ranges: [0, ENC_B) enc->fp16 | [.., +WH_B) Wh->fp16 | [.., +WS_B) ws GEMV | [.., +Z_B) zero ctx
constexpr int ENC_B = (int)((size_t)M_TOTAL * Hh / 2048);  // 32768 blocks, 2048 elems each
constexpr int WH_B  = Hh * Hh / 1024;                      // 1024 blocks, 1024 elems each
constexpr int WS_B  = 256;                                 // 32 b x 8 o-chunks
constexpr int Z_B   = Bb * Hh / 256;                       // 128
constexpr int PRE_BLOCKS = ENC_B + WH_B + WS_B + Z_B;      // 34176

__global__ __launch_bounds__(256) void preprocess_kernel(
    const float* __restrict__ enc, const float* __restrict__ Wh,
    const float* __restrict__ dec, const float* __restrict__ Wsm,
    float* __restrict__ ctx) {
    __shared__ float dec_s[Hh];
    const int bx = blockIdx.x, tid = threadIdx.x;

    if (bx < ENC_B) {
        // enc -> fp16, 8 elements/thread
        size_t i = ((size_t)bx * 256 + tid) * 8;
        float4 v0 = *reinterpret_cast<const float4*>(enc + i);
        float4 v1 = *reinterpret_cast<const float4*>(enc + i + 4);
        uint4 u;
        u.x = pack_h2(v0.x, v0.y); u.y = pack_h2(v0.z, v0.w);
        u.z = pack_h2(v1.x, v1.y); u.w = pack_h2(v1.z, v1.w);
        *reinterpret_cast<uint4*>(g_enc_h + i) = u;
    } else if (bx < ENC_B + WH_B) {
        // Wh -> fp16, 4 elements/thread
        int i = ((bx - ENC_B) * 256 + tid) * 4;
        float4 v = *reinterpret_cast<const float4*>(Wh + i);
        uint2 u;
        u.x = pack_h2(v.x, v.y);
        u.y = pack_h2(v.z, v.w);
        *reinterpret_cast<uint2*>(g_wh_h + i) = u;
    } else if (bx < ENC_B + WH_B + WS_B) {
        // ws[b, oc*128 .. +128) = W_s rows . dec[b]
        int bw = bx - (ENC_B + WH_B);
        int b = bw >> 3, oc = bw & 7;
        int w = tid >> 5, lane = tid & 31;
        *reinterpret_cast<float4*>(&dec_s[tid * 4]) =
            *reinterpret_cast<const float4*>(dec + (size_t)b * Hh + tid * 4);
        __syncthreads();
#pragma unroll 1
        for (int j = 0; j < 16; j++) {
            int o = oc * 128 + w * 16 + j;
            const float* wr = Wsm + (size_t)o * Hh;
            float acc = 0.f;
#pragma unroll
            for (int i = 0; i < 8; i++) {
                int k = (i * 32 + lane) * 4;
                float4 w4 = *reinterpret_cast<const float4*>(wr + k);
                acc += dec_s[k] * w4.x + dec_s[k + 1] * w4.y
                     + dec_s[k + 2] * w4.z + dec_s[k + 3] * w4.w;
            }
#pragma unroll
            for (int off = 16; off; off >>= 1) acc += __shfl_xor_sync(0xffffffffu, acc, off);
            if (lane == 0) g_ws[b * Hh + o] = acc;
        }
    } else {
        // zero ctx (out poisoned by harness)
        int bz = bx - (ENC_B + WH_B + WS_B);
        ctx[bz * 256 + tid] = 0.f;
    }
}

// ================= K1: fused fp16 GEMM + tanh + v-dot -> partial scores =================
// 512 threads, 16 warps in 4(m) x 4(n) grid; warp tile 32(M) x 64(N); BK=64, single sync/step.
__global__ __launch_bounds__(NTHREADS, 1) void attn_scores_kernel(const float* __restrict__ vvec) {
    extern __shared__ char smraw[];
    SmemK1& sm = *reinterpret_cast<SmemK1*>(smraw);

    const int tid = threadIdx.x, wid = tid >> 5, lane = tid & 31;
    const int g = lane >> 2, t = lane & 3;
    const int wm = (wid >> 2) * 32;       // 4 m-groups of 32 rows
    const int wn = (wid & 3) * 64;        // 4 n-groups of 64 cols
    const int m_base = blockIdx.y * BM;
    const int n_base = blockIdx.x * BN;
    const int b = m_base >> 11;

    for (int i = tid; i < BN; i += NTHREADS) {
        sm.ws[i] = g_ws[b * Hh + n_base + i];
        sm.v[i]  = vvec[n_base + i];
    }
    if (tid < BM) sm.rowsum[tid] = 0.f;

    // cp.async chunk coordinates: 16B chunks, 8 per 128B k-row (BK=64 halves)
    const int rA = tid >> 3, cA = tid & 7;     // rows 0..63 (+64), chunk col 0..7
    const __half* srcA = g_enc_h + (size_t)(m_base + rA) * Hh + cA * 8;
    const __half* srcB = g_wh_h  + (size_t)(n_base + rA) * Hh + cA * 8;

    auto issue_stage = [&](int stage, int k0) {
#pragma unroll
        for (int i = 0; i < 2; i++)   // A rows rA, rA+64
            cp_async16(smem_u32(reinterpret_cast<char*>(&sm.A[stage][rA + i * 64][0]) + cA * 16),
                       srcA + (size_t)(i * 64) * Hh + k0);
#pragma unroll
        for (int i = 0; i < 4; i++)   // B rows rA, rA+64, rA+128, rA+192
            cp_async16(smem_u32(reinterpret_cast<char*>(&sm.B[stage][rA + i * 64][0]) + cA * 16),
                       srcB + (size_t)(i * 64) * Hh + k0);
        cp_commit();
    };

    float acc[2][8][4];
#pragma unroll
    for (int ma = 0; ma < 2; ma++)
#pragma unroll
        for (int na = 0; na < 8; na++)
#pragma unroll
            for (int r = 0; r < 4; r++) acc[ma][na][r] = 0.f;

    // ldmatrix lane offset (row stride 144B: 8 rows cover distinct 16B spans mod 128B)
    const int lr = lane & 7, sel = lane >> 3;
    const uint32_t lane_off = (uint32_t)((lr + (sel & 1) * 8) * (LDH * 2) + (sel >> 1) * 16);
    const uint32_t baseA = smem_u32(&sm.A[0][0][0]);
    const uint32_t baseB = smem_u32(&sm.B[0][0][0]);
    constexpr uint32_t A_STRIDE = BM * LDH * 2;   // bytes per stage
    constexpr uint32_t B_STRIDE = BN * LDH * 2;

    // prologue: fill stages 0,1
    issue_stage(0, 0);
    issue_stage(1, BK);

    int p = 0;
#pragma unroll 1
    for (int s = 0; s < NSTEPS; s++) {
        cp_wait1();          // stage s complete (<=1 group in flight)
        __syncthreads();     // visible to all; also: all reads of buffer (s-1) finished

        if (s + 2 < NSTEPS) {
            int nxt = p + 2; if (nxt >= PIPE) nxt -= PIPE;
            issue_stage(nxt, (s + 2) * BK);   // overwrites buffer (s-1): safe after sync
        } else {
            cp_commit();                      // empty group keeps accounting uniform
        }

        uint32_t aw = baseA + p * A_STRIDE + (uint32_t)(wm * (LDH * 2)) + lane_off;
        uint32_t bw = baseB + p * B_STRIDE + (uint32_t)(wn * (LDH * 2)) + lane_off;
#pragma unroll
        for (int ka = 0; ka < 4; ka++) {      // 4 x k16 per stage
            uint32_t af[2][4];
#pragma unroll
            for (int ma = 0; ma < 2; ma++)
                ldmatrix_x4(af[ma], aw + (uint32_t)(ma * 16 * (LDH * 2)) + ka * 32);
            uint32_t bf[8][2];
#pragma unroll
            for (int nb = 0; nb < 4; nb++) {
                uint32_t r[4];
                ldmatrix_x4(r, bw + (uint32_t)(nb * 16 * (LDH * 2)) + ka * 32);
                bf[2 * nb][0] = r[0]; bf[2 * nb + 1][0] = r[1];
                bf[2 * nb][1] = r[2]; bf[2 * nb + 1][1] = r[3];
            }
#pragma unroll
            for (int ma = 0; ma < 2; ma++)
#pragma unroll
                for (int na = 0; na < 8; na++)
                    mma_f16(acc[ma][na], af[ma], bf[na]);
        }

        if (++p >= PIPE) p = 0;
    }

    // epilogue: tanh(acc + ws)*v, reduce over n
#pragma unroll
    for (int ma = 0; ma < 2; ma++) {
        float r0 = 0.f, r1 = 0.f;
#pragma unroll
        for (int na = 0; na < 8; na++) {
            int nl = wn + na * 8 + 2 * t;
            float w0 = sm.ws[nl], w1 = sm.ws[nl + 1];
            float v0 = sm.v[nl],  v1 = sm.v[nl + 1];
            r0 += tanh_fast(acc[ma][na][0] + w0) * v0 + tanh_fast(acc[ma][na][1] + w1) * v1;
            r1 += tanh_fast(acc[ma][na][2] + w0) * v0 + tanh_fast(acc[ma][na][3] + w1) * v1;
        }
        r0 += __shfl_xor_sync(0xffffffffu, r0, 1);
        r0 += __shfl_xor_sync(0xffffffffu, r0, 2);
        r1 += __shfl_xor_sync(0xffffffffu, r1, 1);
        r1 += __shfl_xor_sync(0xffffffffu, r1, 2);
        if (t == 0) {
            atomicAdd(&sm.rowsum[wm + ma * 16 + g], r0);
            atomicAdd(&sm.rowsum[wm + ma * 16 + g + 8], r1);
        }
    }
    __syncthreads();
    if (tid < BM) g_part[blockIdx.x][m_base + tid] = sm.rowsum[tid];
}

// ================= K2: fused softmax + context =================
// grid (1, Bb, 32), block 256. Each block recomputes softmax for batch b from g_part
// (L2-resident, ~32KB/block), z-block writes its 64-row attw slice, then does the
// context partial for its 64 s-rows with uint4 loads + spread atomics into pre-zeroed ctx.
__global__ __launch_bounds__(256) void ctx_softmax_kernel(float* __restrict__ attw,
                                                          float* __restrict__ out) {
    __shared__ float sc[Ss];
    __shared__ float red[256];
    const int b = blockIdx.y;
    const int z = blockIdx.z;
    const int tid = threadIdx.x;

    // --- softmax over S for batch b (same arithmetic as the old softmax_kernel) ---
    float mx = -1e30f;
    for (int i = tid; i < Ss; i += 256) {
        int idx = b * Ss + i;
        float v = g_part[0][idx] + g_part[1][idx] + g_part[2][idx] + g_part[3][idx];
        sc[i] = v;
        mx = fmaxf(mx, v);
    }
    red[tid] = mx; __syncthreads();
    for (int o = 128; o; o >>= 1) { if (tid < o) red[tid] = fmaxf(red[tid], red[tid + o]); __syncthreads(); }
    mx = red[0]; __syncthreads();
    float sum = 0.f;
    for (int i = tid; i < Ss; i += 256) { float e = __expf(sc[i] - mx); sc[i] = e; sum += e; }
    red[tid] = sum; __syncthreads();
    for (int o = 128; o; o >>= 1) { if (tid < o) red[tid] += red[tid + o]; __syncthreads(); }
    const float inv = 1.f / red[0];

    const int s0 = z * 64;
    if (tid < 64) attw[b * Ss + s0 + tid] = sc[s0 + tid] * inv;

    // --- context partial for s in [s0, s0+64) ---
    const int h8 = tid & 127;          // column group: halves [h8*8, h8*8+8)
    const int sp = tid >> 7;           // s parity 0/1
    const uint4* e = reinterpret_cast<const uint4*>(g_enc_h + (size_t)(b * Ss + s0) * Hh) + h8;
    constexpr int ROW_U4 = Hh / 8;     // 128 uint4 per s-row

    float acc[8];
#pragma unroll
    for (int j = 0; j < 8; j++) acc[j] = 0.f;

#pragma unroll 8
    for (int s = sp; s < 64; s += 2) {
        uint4 u = e[(size_t)s * ROW_U4];
        float wgt = sc[s0 + s] * inv;
        float2 f0 = __half22float2(*reinterpret_cast<__half2*>(&u.x));
        float2 f1 = __half22float2(*reinterpret_cast<__half2*>(&u.y));
        float2 f2 = __half22float2(*reinterpret_cast<__half2*>(&u.z));
        float2 f3 = __half22float2(*reinterpret_cast<__half2*>(&u.w));
        acc[0] += wgt * f0.x; acc[1] += wgt * f0.y;
        acc[2] += wgt * f1.x; acc[3] += wgt * f1.y;
        acc[4] += wgt * f2.x; acc[5] += wgt * f2.y;
        acc[6] += wgt * f3.x; acc[7] += wgt * f3.y;
    }

    float* dst = out + b * Hh + h8 * 8;
#pragma unroll
    for (int j = 0; j < 8; j++) atomicAdd(&dst[j], acc[j]);
}

// ================= launcher =================
extern "C" void kernel_launch(void* const* d_in, const int* in_sizes, int n_in,
                              void* d_out, int out_size) {
    (void)in_sizes; (void)n_in; (void)out_size;
    const float* dec = (const float*)d_in[0];   // [32,1024]
    const float* enc = (const float*)d_in[1];   // [32,2048,1024]
    const float* Wh  = (const float*)d_in[2];   // [1024,1024]
    const float* Wsm = (const float*)d_in[3];   // [1024,1024]
    const float* v   = (const float*)d_in[4];   // [1024]
    float* out  = (float*)d_out;
    float* ctx  = out;                 // [32,1024]
    float* attw = out + Bb * Hh;       // [32,2048]

    cudaFuncSetAttribute(attn_scores_kernel, cudaFuncAttributeMaxDynamicSharedMemorySize,
                         (int)sizeof(SmemK1));

    preprocess_kernel<<<PRE_BLOCKS, 256>>>(enc, Wh, dec, Wsm, ctx);
    attn_scores_kernel<<<dim3(NT, M_TOTAL / BM), NTHREADS, sizeof(SmemK1)>>>(v);
    ctx_softmax_kernel<<<dim3(1, Bb, 32), 256>>>(attw, ctx);
}

// round 17
// speedup vs baseline: 1.3778x; 1.0216x over previous
#include <cuda_runtime.h>
#include <cuda_fp16.h>
#include <cstdint>

#define DEVINL __device__ __forceinline__

// ---------------- problem sizes ----------------
constexpr int Bb = 32, Ss = 2048, Hh = 1024;
constexpr int M_TOTAL = Bb * Ss;          // 65536
constexpr int BM = 128, BN = 256, BK = 64;   // K-step = 64 elements
constexpr int NSTEPS = Hh / BK;           // 16
constexpr int NT = Hh / BN;               // 4 N-tiles
constexpr int LDH = 72;                   // padded smem row stride in halves (144B)
constexpr int PIPE = 3;                   // cp.async stages
constexpr int NTHREADS = 512;             // 16 warps

// ---------------- scratch (no allocs allowed) ----------------
__device__ float  g_ws[Bb * Hh];          // W_s @ dec
__device__ __half g_wh_h[Hh * Hh];        // fp16 W_h
__device__ __half g_enc_h[(size_t)M_TOTAL * Hh];  // fp16 encoder (128 MB)
__device__ float  g_part[NT][M_TOTAL];    // partial scores per N-tile

struct SmemK1 {
    __half A[PIPE][BM][LDH];   // 3*128*144B = 55,296 B
    __half B[PIPE][BN][LDH];   // 3*256*144B = 110,592 B
    float ws[BN];
    float v[BN];
    float rowsum[BM];
};

// ---------------- helpers ----------------
DEVINL uint32_t smem_u32(const void* p) {
    uint32_t a;
    asm("{ .reg .u64 t; cvta.to.shared.u64 t, %1; cvt.u32.u64 %0, t; }" : "=r"(a) : "l"(p));
    return a;
}
DEVINL float tanh_fast(float x) {
    float r;
    asm("tanh.approx.f32 %0, %1;" : "=f"(r) : "f"(x));
    return r;
}
DEVINL void cp_async16(uint32_t dst, const void* src) {
    asm volatile("cp.async.cg.shared.global [%0], [%1], 16;" :: "r"(dst), "l"(src));
}
DEVINL void cp_commit() { asm volatile("cp.async.commit_group;"); }
DEVINL void cp_wait1()  { asm volatile("cp.async.wait_group 1;"); }

DEVINL void ldmatrix_x4(uint32_t r[4], uint32_t addr) {
    asm volatile("ldmatrix.sync.aligned.m8n8.x4.shared.b16 {%0,%1,%2,%3}, [%4];"
                 : "=r"(r[0]), "=r"(r[1]), "=r"(r[2]), "=r"(r[3]) : "r"(addr));
}
DEVINL void mma_f16(float c[4], const uint32_t a[4], const uint32_t b[2]) {
    asm volatile(
        "mma.sync.aligned.m16n8k16.row.col.f32.f16.f16.f32 "
        "{%0,%1,%2,%3}, {%4,%5,%6,%7}, {%8,%9}, {%0,%1,%2,%3};"
        : "+f"(c[0]), "+f"(c[1]), "+f"(c[2]), "+f"(c[3])
        : "r"(a[0]), "r"(a[1]), "r"(a[2]), "r"(a[3]), "r"(b[0]), "r"(b[1]));
}
DEVINL uint32_t pack_h2(float lo, float hi) {
    __half2 h = __floats2half2_rn(lo, hi);
    return *reinterpret_cast<uint32_t*>(&h);
}

// ================= K0: fused preprocessing, one launch =================
// Block ranges: [0, ENC_B) enc->fp16 | [.., +WH_B) Wh->fp16 | [.., +WS_B) ws GEMV | [.., +Z_B) zero ctx
constexpr int ENC_B = (int)((size_t)M_TOTAL * Hh / 4096);  // 16384 blocks, 4096 elems each
constexpr int WH_B  = Hh * Hh / 2048;                      // 512 blocks, 2048 elems each
constexpr int WS_B  = 256;                                 // 32 b x 8 o-chunks
constexpr int Z_B   = Bb * Hh / 256;                       // 128
constexpr int PRE_BLOCKS = ENC_B + WH_B + WS_B + Z_B;      // 17280

__global__ __launch_bounds__(256) void preprocess_kernel(
    const float* __restrict__ enc, const float* __restrict__ Wh,
    const float* __restrict__ dec, const float* __restrict__ Wsm,
    float* __restrict__ ctx) {
    __shared__ float dec_s[Hh];
    const int bx = blockIdx.x, tid = threadIdx.x;

    if (bx < ENC_B) {
        // enc -> fp16, 16 elements/thread; 4 independent loads batched (MLP=4)
        size_t i = ((size_t)bx * 256 + tid) * 16;
        float4 v0 = *reinterpret_cast<const float4*>(enc + i);
        float4 v1 = *reinterpret_cast<const float4*>(enc + i + 4);
        float4 v2 = *reinterpret_cast<const float4*>(enc + i + 8);
        float4 v3 = *reinterpret_cast<const float4*>(enc + i + 12);
        uint4 u0, u1;
        u0.x = pack_h2(v0.x, v0.y); u0.y = pack_h2(v0.z, v0.w);
        u0.z = pack_h2(v1.x, v1.y); u0.w = pack_h2(v1.z, v1.w);
        u1.x = pack_h2(v2.x, v2.y); u1.y = pack_h2(v2.z, v2.w);
        u1.z = pack_h2(v3.x, v3.y); u1.w = pack_h2(v3.z, v3.w);
        *reinterpret_cast<uint4*>(g_enc_h + i)     = u0;
        *reinterpret_cast<uint4*>(g_enc_h + i + 8) = u1;
    } else if (bx < ENC_B + WH_B) {
        // Wh -> fp16, 8 elements/thread; 2 loads batched
        int i = ((bx - ENC_B) * 256 + tid) * 8;
        float4 v0 = *reinterpret_cast<const float4*>(Wh + i);
        float4 v1 = *reinterpret_cast<const float4*>(Wh + i + 4);
        uint4 u;
        u.x = pack_h2(v0.x, v0.y); u.y = pack_h2(v0.z, v0.w);
        u.z = pack_h2(v1.x, v1.y); u.w = pack_h2(v1.z, v1.w);
        *reinterpret_cast<uint4*>(g_wh_h + i) = u;
    } else if (bx < ENC_B + WH_B + WS_B) {
        // ws[b, oc*128 .. +128) = W_s rows . dec[b]
        int bw = bx - (ENC_B + WH_B);
        int b = bw >> 3, oc = bw & 7;
        int w = tid >> 5, lane = tid & 31;
        *reinterpret_cast<float4*>(&dec_s[tid * 4]) =
            *reinterpret_cast<const float4*>(dec + (size_t)b * Hh + tid * 4);
        __syncthreads();
#pragma unroll 1
        for (int j = 0; j < 16; j++) {
            int o = oc * 128 + w * 16 + j;
            const float* wr = Wsm + (size_t)o * Hh;
            float acc = 0.f;
#pragma unroll
            for (int i = 0; i < 8; i++) {
                int k = (i * 32 + lane) * 4;
                float4 w4 = *reinterpret_cast<const float4*>(wr + k);
                acc += dec_s[k] * w4.x + dec_s[k + 1] * w4.y
                     + dec_s[k + 2] * w4.z + dec_s[k + 3] * w4.w;
            }
#pragma unroll
            for (int off = 16; off; off >>= 1) acc += __shfl_xor_sync(0xffffffffu, acc, off);
            if (lane == 0) g_ws[b * Hh + o] = acc;
        }
    } else {
        // zero ctx (out poisoned by harness)
        int bz = bx - (ENC_B + WH_B + WS_B);
        ctx[bz * 256 + tid] = 0.f;
    }
}

// ================= K1: fused fp16 GEMM + tanh + v-dot -> partial scores =================
// 512 threads, 16 warps in 4(m) x 4(n) grid; warp tile 32(M) x 64(N); BK=64, single sync/step.
__global__ __launch_bounds__(NTHREADS, 1) void attn_scores_kernel(const float* __restrict__ vvec) {
    extern __shared__ char smraw[];
    SmemK1& sm = *reinterpret_cast<SmemK1*>(smraw);

    const int tid = threadIdx.x, wid = tid >> 5, lane = tid & 31;
    const int g = lane >> 2, t = lane & 3;
    const int wm = (wid >> 2) * 32;       // 4 m-groups of 32 rows
    const int wn = (wid & 3) * 64;        // 4 n-groups of 64 cols
    const int m_base = blockIdx.y * BM;
    const int n_base = blockIdx.x * BN;
    const int b = m_base >> 11;

    for (int i = tid; i < BN; i += NTHREADS) {
        sm.ws[i] = g_ws[b * Hh + n_base + i];
        sm.v[i]  = vvec[n_base + i];
    }
    if (tid < BM) sm.rowsum[tid] = 0.f;

    // cp.async chunk coordinates: 16B chunks, 8 per 128B k-row (BK=64 halves)
    const int rA = tid >> 3, cA = tid & 7;     // rows 0..63 (+64), chunk col 0..7
    const __half* srcA = g_enc_h + (size_t)(m_base + rA) * Hh + cA * 8;
    const __half* srcB = g_wh_h  + (size_t)(n_base + rA) * Hh + cA * 8;

    auto issue_stage = [&](int stage, int k0) {
#pragma unroll
        for (int i = 0; i < 2; i++)   // A rows rA, rA+64
            cp_async16(smem_u32(reinterpret_cast<char*>(&sm.A[stage][rA + i * 64][0]) + cA * 16),
                       srcA + (size_t)(i * 64) * Hh + k0);
#pragma unroll
        for (int i = 0; i < 4; i++)   // B rows rA, rA+64, rA+128, rA+192
            cp_async16(smem_u32(reinterpret_cast<char*>(&sm.B[stage][rA + i * 64][0]) + cA * 16),
                       srcB + (size_t)(i * 64) * Hh + k0);
        cp_commit();
    };

    float acc[2][8][4];
#pragma unroll
    for (int ma = 0; ma < 2; ma++)
#pragma unroll
        for (int na = 0; na < 8; na++)
#pragma unroll
            for (int r = 0; r < 4; r++) acc[ma][na][r] = 0.f;

    // ldmatrix lane offset (row stride 144B: 8 rows cover distinct 16B spans mod 128B)
    const int lr = lane & 7, sel = lane >> 3;
    const uint32_t lane_off = (uint32_t)((lr + (sel & 1) * 8) * (LDH * 2) + (sel >> 1) * 16);
    const uint32_t baseA = smem_u32(&sm.A[0][0][0]);
    const uint32_t baseB = smem_u32(&sm.B[0][0][0]);
    constexpr uint32_t A_STRIDE = BM * LDH * 2;   // bytes per stage
    constexpr uint32_t B_STRIDE = BN * LDH * 2;

    // prologue: fill stages 0,1
    issue_stage(0, 0);
    issue_stage(1, BK);

    int p = 0;
#pragma unroll 1
    for (int s = 0; s < NSTEPS; s++) {
        cp_wait1();          // stage s complete (<=1 group in flight)
        __syncthreads();     // visible to all; also: all reads of buffer (s-1) finished

        if (s + 2 < NSTEPS) {
            int nxt = p + 2; if (nxt >= PIPE) nxt -= PIPE;
            issue_stage(nxt, (s + 2) * BK);   // overwrites buffer (s-1): safe after sync
        } else {
            cp_commit();                      // empty group keeps accounting uniform
        }

        uint32_t aw = baseA + p * A_STRIDE + (uint32_t)(wm * (LDH * 2)) + lane_off;
        uint32_t bw = baseB + p * B_STRIDE + (uint32_t)(wn * (LDH * 2)) + lane_off;
#pragma unroll
        for (int ka = 0; ka < 4; ka++) {      // 4 x k16 per stage
            uint32_t af[2][4];
#pragma unroll
            for (int ma = 0; ma < 2; ma++)
                ldmatrix_x4(af[ma], aw + (uint32_t)(ma * 16 * (LDH * 2)) + ka * 32);
            uint32_t bf[8][2];
#pragma unroll
            for (int nb = 0; nb < 4; nb++) {
                uint32_t r[4];
                ldmatrix_x4(r, bw + (uint32_t)(nb * 16 * (LDH * 2)) + ka * 32);
                bf[2 * nb][0] = r[0]; bf[2 * nb + 1][0] = r[1];
                bf[2 * nb][1] = r[2]; bf[2 * nb + 1][1] = r[3];
            }
#pragma unroll
            for (int ma = 0; ma < 2; ma++)
#pragma unroll
                for (int na = 0; na < 8; na++)
                    mma_f16(acc[ma][na], af[ma], bf[na]);
        }

        if (++p >= PIPE) p = 0;
    }

    // epilogue: tanh(acc + ws)*v, reduce over n
#pragma unroll
    for (int ma = 0; ma < 2; ma++) {
        float r0 = 0.f, r1 = 0.f;
#pragma unroll
        for (int na = 0; na < 8; na++) {
            int nl = wn + na * 8 + 2 * t;
            float w0 = sm.ws[nl], w1 = sm.ws[nl + 1];
            float v0 = sm.v[nl],  v1 = sm.v[nl + 1];
            r0 += tanh_fast(acc[ma][na][0] + w0) * v0 + tanh_fast(acc[ma][na][1] + w1) * v1;
            r1 += tanh_fast(acc[ma][na][2] + w0) * v0 + tanh_fast(acc[ma][na][3] + w1) * v1;
        }
        r0 += __shfl_xor_sync(0xffffffffu, r0, 1);
        r0 += __shfl_xor_sync(0xffffffffu, r0, 2);
        r1 += __shfl_xor_sync(0xffffffffu, r1, 1);
        r1 += __shfl_xor_sync(0xffffffffu, r1, 2);
        if (t == 0) {
            atomicAdd(&sm.rowsum[wm + ma * 16 + g], r0);
            atomicAdd(&sm.rowsum[wm + ma * 16 + g + 8], r1);
        }
    }
    __syncthreads();
    if (tid < BM) g_part[blockIdx.x][m_base + tid] = sm.rowsum[tid];
}

// ================= K2: fused softmax + context =================
// grid (1, Bb, 32), block 256. Each block recomputes softmax for batch b from g_part
// (L2-resident), z-block writes its 64-row attw slice, then does the context partial
// for its 64 s-rows with uint4 loads + spread atomics into pre-zeroed ctx.
__global__ __launch_bounds__(256) void ctx_softmax_kernel(float* __restrict__ attw,
                                                          float* __restrict__ out) {
    __shared__ float sc[Ss];
    __shared__ float red[256];
    const int b = blockIdx.y;
    const int z = blockIdx.z;
    const int tid = threadIdx.x;

    // --- softmax over S for batch b ---
    float mx = -1e30f;
    for (int i = tid; i < Ss; i += 256) {
        int idx = b * Ss + i;
        float v = g_part[0][idx] + g_part[1][idx] + g_part[2][idx] + g_part[3][idx];
        sc[i] = v;
        mx = fmaxf(mx, v);
    }
    red[tid] = mx; __syncthreads();
    for (int o = 128; o; o >>= 1) { if (tid < o) red[tid] = fmaxf(red[tid], red[tid + o]); __syncthreads(); }
    mx = red[0]; __syncthreads();
    float sum = 0.f;
    for (int i = tid; i < Ss; i += 256) { float e = __expf(sc[i] - mx); sc[i] = e; sum += e; }
    red[tid] = sum; __syncthreads();
    for (int o = 128; o; o >>= 1) { if (tid < o) red[tid] += red[tid + o]; __syncthreads(); }
    const float inv = 1.f / red[0];

    const int s0 = z * 64;
    if (tid < 64) attw[b * Ss + s0 + tid] = sc[s0 + tid] * inv;

    // --- context partial for s in [s0, s0+64) ---
    const int h8 = tid & 127;          // column group: halves [h8*8, h8*8+8)
    const int sp = tid >> 7;           // s parity 0/1
    const uint4* e = reinterpret_cast<const uint4*>(g_enc_h + (size_t)(b * Ss + s0) * Hh) + h8;
    constexpr int ROW_U4 = Hh / 8;     // 128 uint4 per s-row

    float acc[8];
#pragma unroll
    for (int j = 0; j < 8; j++) acc[j] = 0.f;

#pragma unroll 8
    for (int s = sp; s < 64; s += 2) {
        uint4 u = e[(size_t)s * ROW_U4];
        float wgt = sc[s0 + s] * inv;
        float2 f0 = __half22float2(*reinterpret_cast<__half2*>(&u.x));
        float2 f1 = __half22float2(*reinterpret_cast<__half2*>(&u.y));
        float2 f2 = __half22float2(*reinterpret_cast<__half2*>(&u.z));
        float2 f3 = __half22float2(*reinterpret_cast<__half2*>(&u.w));
        acc[0] += wgt * f0.x; acc[1] += wgt * f0.y;
        acc[2] += wgt * f1.x; acc[3] += wgt * f1.y;
        acc[4] += wgt * f2.x; acc[5] += wgt * f2.y;
        acc[6] += wgt * f3.x; acc[7] += wgt * f3.y;
    }

    float* dst = out + b * Hh + h8 * 8;
#pragma unroll
    for (int j = 0; j < 8; j++) atomicAdd(&dst[j], acc[j]);
}

// ================= launcher =================
extern "C" void kernel_launch(void* const* d_in, const int* in_sizes, int n_in,
                              void* d_out, int out_size) {
    (void)in_sizes; (void)n_in; (void)out_size;
    const float* dec = (const float*)d_in[0];   // [32,1024]
    const float* enc = (const float*)d_in[1];   // [32,2048,1024]
    const float* Wh  = (const float*)d_in[2];   // [1024,1024]
    const float* Wsm = (const float*)d_in[3];   // [1024,1024]
    const float* v   = (const float*)d_in[4];   // [1024]
    float* out  = (float*)d_out;
    float* ctx  = out;                 // [32,1024]
    float* attw = out + Bb * Hh;       // [32,2048]

    cudaFuncSetAttribute(attn_scores_kernel, cudaFuncAttributeMaxDynamicSharedMemorySize,
                         (int)sizeof(SmemK1));

    preprocess_kernel<<<PRE_BLOCKS, 256>>>(enc, Wh, dec, Wsm, ctx);
    attn_scores_kernel<<<dim3(NT, M_TOTAL / BM), NTHREADS, sizeof(SmemK1)>>>(v);
    ctx_softmax_kernel<<<dim3(1, Bb, 32), 256>>>(attw, ctx);
}